// round 13
// baseline (speedup 1.0000x reference)
#include <cuda_runtime.h>
#include <math.h>

#define BSZ 8
#define TT  2048
#define DD  1024
#define FFD 2048
#define EE  6
#define NTOK (BSZ*TT)
#define NF  1025
#define NFP 1056
#define KI  (2*NFP)

typedef unsigned int u32;
typedef unsigned long long u64;

// ---------------- scratch ----------------
__device__ float g_gate[NTOK*EE];
__device__ float g_gsh[NTOK];
__device__ float g_probs[NTOK*EE];
__device__ int   g_idx[NTOK*2];
__device__ float g_H[NTOK*(long)FFD];
__device__ float g_xc[NTOK*(long)DD];
__device__ float g_xT[BSZ*(long)DD*TT];
__device__ float g_cat[BSZ*(long)NF*2048];
__device__ float g_fo[BSZ*(long)NF*2048];
__device__ float g_foT[BSZ*(long)DD*KI];
__device__ float g_CiSi[(long)TT*KI];
__device__ float g_Acos[(long)NF*TT];
__device__ float g_Asin[(long)NF*TT];
__device__ float g_WT[36u*1024u*1024u];

// ---------------- init: DFT bases ----------------
__global__ void init_fwd() {
    int i = blockIdx.x*blockDim.x + threadIdx.x;
    if (i >= NF*TT) return;
    int k = i / TT, t = i % TT;
    int idx = (k*t) & (TT-1);
    float fr = (float)idx / (float)(TT/2);
    g_Acos[i] = cospif(fr);
    g_Asin[i] = -sinpif(fr);
}
__global__ void init_inv() {
    long i = (long)blockIdx.x*blockDim.x + threadIdx.x;
    if (i >= (long)TT*KI) return;
    int t = (int)(i / KI), kk = (int)(i % KI);
    int isimag = kk >= NFP;
    int k = isimag ? kk - NFP : kk;
    float v = 0.f;
    const float invT = 1.0f/(float)TT;
    if (k < NF) {
        int idx = (k*t) & (TT-1);
        float fr = (float)idx / (float)(TT/2);
        if (!isimag) {
            if (k == 0) v = invT;
            else if (k == TT/2) v = ((t & 1) ? -invT : invT);
            else v = 2.0f*cospif(fr)*invT;
        } else {
            if (k != 0 && k != TT/2) v = -2.0f*sinpif(fr)*invT;
        }
    }
    g_CiSi[i] = v;
}

// ---------------- router + gates ----------------
__global__ void router_kernel(const float* __restrict__ x,
                              const float* __restrict__ rw, const float* __restrict__ rb,
                              const float* __restrict__ gw, const float* __restrict__ gb) {
    __shared__ float sx[DD];
    __shared__ float slog[8];
    int tok = blockIdx.x;
    const float* xr = x + (long)tok * DD;
    for (int i = threadIdx.x; i < DD; i += blockDim.x) sx[i] = xr[i];
    __syncthreads();
    int w = threadIdx.x >> 5, lane = threadIdx.x & 31;
    if (w < 7) {
        float acc = 0.f;
        if (w < 6) { for (int i = lane; i < DD; i += 32) acc += sx[i] * rw[i*EE + w]; }
        else       { for (int i = lane; i < DD; i += 32) acc += sx[i] * gw[i]; }
        #pragma unroll
        for (int o = 16; o > 0; o >>= 1) acc += __shfl_down_sync(0xffffffffu, acc, o);
        if (lane == 0) slog[w] = acc + (w < 6 ? rb[w] : gb[0]);
    }
    __syncthreads();
    if (threadIdx.x == 0) {
        float l[EE], mx = -1e30f;
        for (int e = 0; e < EE; e++) { l[e] = slog[e]; mx = fmaxf(mx, l[e]); }
        float den = 0.f;
        for (int e = 0; e < EE; e++) { l[e] = expf(l[e]-mx); den += l[e]; }
        float p[EE];
        for (int e = 0; e < EE; e++) { p[e] = l[e]/den; g_probs[tok*EE+e] = p[e]; g_gate[tok*EE+e] = 0.f; }
        int i1 = 0; for (int e = 1; e < EE; e++) if (p[e] > p[i1]) i1 = e;
        int i2 = (i1==0)?1:0;
        for (int e = 0; e < EE; e++) if (e != i1 && p[e] > p[i2]) i2 = e;
        g_gate[tok*EE+i1] = p[i1];
        g_gate[tok*EE+i2] = p[i2];
        g_idx[tok*2]   = i1;
        g_idx[tok*2+1] = i2;
        g_gsh[tok] = 1.0f/(1.0f+expf(-slog[6]));
    }
}

__global__ void aux_kernel(float* __restrict__ out, int out_size) {
    __shared__ float sf[EE][256];
    __shared__ int   si[EE][256];
    float imp[EE]; int cnt[EE];
    for (int e = 0; e < EE; e++) { imp[e] = 0.f; cnt[e] = 0; }
    for (int n = threadIdx.x; n < NTOK; n += 256) {
        #pragma unroll
        for (int e = 0; e < EE; e++) imp[e] += g_probs[n*EE+e];
        cnt[g_idx[n*2]]++; cnt[g_idx[n*2+1]]++;
    }
    for (int e = 0; e < EE; e++) { sf[e][threadIdx.x] = imp[e]; si[e][threadIdx.x] = cnt[e]; }
    __syncthreads();
    for (int s = 128; s > 0; s >>= 1) {
        if (threadIdx.x < s)
            for (int e = 0; e < EE; e++) {
                sf[e][threadIdx.x] += sf[e][threadIdx.x+s];
                si[e][threadIdx.x] += si[e][threadIdx.x+s];
            }
        __syncthreads();
    }
    if (threadIdx.x == 0) {
        float aux = 0.f;
        for (int e = 0; e < EE; e++)
            aux += ((float)si[e][0] / (2.0f*(float)NTOK)) * (sf[e][0] / (float)NTOK);
        out[out_size-1] = (float)EE * aux;
    }
}

// ---------------- conv ----------------
__global__ void conv_kernel(const float* __restrict__ x, const float* __restrict__ ck,
                            float* __restrict__ xc) {
    long i = (long)blockIdx.x*blockDim.x + threadIdx.x;
    if (i >= (long)NTOK*DD) return;
    int d = (int)(i % DD);
    long td = i / DD;
    int t = (int)(td % TT);
    float k0 = ck[d*3], k1 = ck[d*3+1], k2 = ck[d*3+2];
    float c = x[i]*k1;
    if (t > 0)     c += x[i-DD]*k0;
    if (t < TT-1)  c += x[i+DD]*k2;
    xc[i] = x[i] + c;
}

// ---------------- transposes ----------------
__global__ void transpose_k(const float* __restrict__ in, float* __restrict__ out,
                            int R, int C) {
    __shared__ float t[32][33];
    long bo = (long)blockIdx.z * R * C;
    in += bo; out += bo;
    int c0 = blockIdx.x*32, r0 = blockIdx.y*32;
    #pragma unroll
    for (int i = 0; i < 4; i++) {
        int r = r0 + threadIdx.y + i*8, c = c0 + threadIdx.x;
        t[threadIdx.y+i*8][threadIdx.x] = (r < R && c < C) ? in[(long)r*C + c] : 0.f;
    }
    __syncthreads();
    #pragma unroll
    for (int i = 0; i < 4; i++) {
        int c = c0 + threadIdx.y + i*8, r = r0 + threadIdx.x;
        if (c < C && r < R) out[(long)c*R + r] = t[threadIdx.x][threadIdx.y+i*8];
    }
}

__global__ void transpose_fo(const float* __restrict__ fo, float* __restrict__ foT,
                             int coloff, int kbase) {
    __shared__ float t[32][33];
    int b = blockIdx.z;
    const float* in = fo + (long)b*NF*2048;
    float* ob = foT + (long)b*DD*KI;
    int k0 = blockIdx.x*32, d0 = blockIdx.y*32;
    #pragma unroll
    for (int i = 0; i < 4; i++) {
        int k = k0 + threadIdx.y + i*8;
        t[threadIdx.y+i*8][threadIdx.x] = (k < NF) ? in[(long)k*2048 + coloff + d0 + threadIdx.x] : 0.f;
    }
    __syncthreads();
    #pragma unroll
    for (int i = 0; i < 4; i++) {
        int d = d0 + threadIdx.y + i*8;
        ob[(long)d*KI + kbase + k0 + threadIdx.x] = t[threadIdx.x][threadIdx.y+i*8];
    }
}

// ================= tf32 mma.sync GEMM, 64x64 warp tile, 3-stage pipeline =================
// D[M,N] = A[M,K] @ Bt[N,K]^T; A,Bt K-major. K%16==0, N%128==0, M ragged OK.
#define SPAD 20
#define NSTAGE 3
#define TILE_FLOATS (128*SPAD)
#define SMEM_DYN (NSTAGE*2*TILE_FLOATS*4)

__device__ __forceinline__ float gelu_f(float v) {
    return 0.5f*v*(1.0f + erff(v*0.7071067811865475f));
}
__device__ __forceinline__ void cp16(u32 dst, const void* src, int sz) {
    asm volatile("cp.async.ca.shared.global [%0], [%1], 16, %2;" :: "r"(dst), "l"(src), "r"(sz));
}
__device__ __forceinline__ u32 tf32r(float f) {
    u32 r; asm("cvt.rna.tf32.f32 %0, %1;" : "=r"(r) : "f"(f)); return r;
}
__device__ __forceinline__ void mma8(float* c, const u32* a, const u32* b) {
    asm volatile("mma.sync.aligned.m16n8k8.row.col.f32.tf32.tf32.f32 "
        "{%0,%1,%2,%3}, {%4,%5,%6,%7}, {%8,%9}, {%0,%1,%2,%3};"
        : "+f"(c[0]), "+f"(c[1]), "+f"(c[2]), "+f"(c[3])
        : "r"(a[0]), "r"(a[1]), "r"(a[2]), "r"(a[3]), "r"(b[0]), "r"(b[1]));
}

// EPI: 0 store, 1 gelu(v+b), 2 (v+b), 3 out+=(v+b)*gate[r,eid], 4 out=(v+b)*gsh[r],
//      5 out += v*gate[z*TT+r, eid]
template<int EPI>
__global__ void __launch_bounds__(128, 2)
mma_gemm(const float* __restrict__ A, const float* __restrict__ B,
         float* __restrict__ C, const float* __restrict__ bias,
         int M, int N, int K, int lda, int ldb, int ldc,
         long sA, long sB, long sC, int eid)
{
    extern __shared__ float smp[];
    float* Asm = smp;
    float* Bsm = smp + NSTAGE*TILE_FLOATS;
    A += (long)blockIdx.z * sA;
    B += (long)blockIdx.z * sB;
    C += (long)blockIdx.z * sC;
    const int row0 = blockIdx.y * 128, col0 = blockIdx.x * 128;
    const int tid = threadIdx.x, lane = tid & 31, wid = tid >> 5;
    const int wm = (wid >> 1) * 64, wn = (wid & 1) * 64;
    const u32 sa = (u32)__cvta_generic_to_shared(Asm);
    const u32 sb = (u32)__cvta_generic_to_shared(Bsm);
    const int g4 = lane >> 2, q4 = lane & 3;

    float acc[4][8][4];
    #pragma unroll
    for (int mi = 0; mi < 4; mi++)
        #pragma unroll
        for (int ni = 0; ni < 8; ni++)
            #pragma unroll
            for (int q = 0; q < 4; q++) acc[mi][ni][q] = 0.f;

    const int nk = K / 16;

    // loader: thread t owns A row t and B row t of the 128-row tiles (4x16B each)
    auto loadStage = [&](int ic, int buf) {
        int k0 = ic * 16;
        int gm = row0 + tid;
        bool ok = gm < M;
        const float* srcA = A + (ok ? ((long)gm*lda + k0) : 0);
        const float* srcB = B + (long)(col0 + tid)*ldb + k0;
        #pragma unroll
        for (int q = 0; q < 4; q++) {
            cp16(sa + (u32)(((buf*128 + tid)*SPAD + q*4)*4), srcA + q*4, ok ? 16 : 0);
            cp16(sb + (u32)(((buf*128 + tid)*SPAD + q*4)*4), srcB + q*4, 16);
        }
        asm volatile("cp.async.commit_group;" ::: "memory");
    };

    loadStage(0, 0);
    if (nk > 1) loadStage(1, 1);

    int buf = 0;
    for (int ic = 0; ic < nk; ic++) {
        asm volatile("cp.async.wait_group 1;" ::: "memory");
        __syncthreads();
        if (ic + 2 < nk) loadStage(ic + 2, (ic + 2) % NSTAGE);

        const float* Ab = Asm + buf*TILE_FLOATS;
        const float* Bb = Bsm + buf*TILE_FLOATS;
        #pragma unroll
        for (int ks = 0; ks < 2; ks++) {
            u32 areg[4][4], breg[8][2];
            #pragma unroll
            for (int mi = 0; mi < 4; mi++) {
                const float* ap = Ab + (wm + mi*16 + g4)*SPAD + ks*8 + q4;
                areg[mi][0] = tf32r(ap[0]);
                areg[mi][1] = tf32r(ap[8*SPAD]);
                areg[mi][2] = tf32r(ap[4]);
                areg[mi][3] = tf32r(ap[8*SPAD + 4]);
            }
            #pragma unroll
            for (int ni = 0; ni < 8; ni++) {
                const float* bp = Bb + (wn + ni*8 + g4)*SPAD + ks*8 + q4;
                breg[ni][0] = tf32r(bp[0]);
                breg[ni][1] = tf32r(bp[4]);
            }
            #pragma unroll
            for (int mi = 0; mi < 4; mi++)
                #pragma unroll
                for (int ni = 0; ni < 8; ni++)
                    mma8(acc[mi][ni], areg[mi], breg[ni]);
        }
        buf = (buf + 1 == NSTAGE) ? 0 : buf + 1;
    }

    // ---- epilogue (C frag: rows g4 / g4+8, cols 2*q4, 2*q4+1) ----
    #pragma unroll
    for (int mi = 0; mi < 4; mi++) {
        #pragma unroll
        for (int h = 0; h < 2; h++) {
            int r = row0 + wm + mi*16 + g4 + h*8;
            if (r >= M) continue;
            float gmul = 1.f;
            if (EPI == 3) gmul = g_gate[(long)r*EE + eid];
            if (EPI == 4) gmul = g_gsh[r];
            if (EPI == 5) gmul = g_gate[((long)blockIdx.z*TT + r)*EE + eid];
            float* crow = C + (long)r*ldc;
            #pragma unroll
            for (int ni = 0; ni < 8; ni++) {
                int col = col0 + wn + ni*8 + 2*q4;
                float v0 = acc[mi][ni][h*2 + 0];
                float v1 = acc[mi][ni][h*2 + 1];
                if (EPI == 1 || EPI == 2 || EPI == 3 || EPI == 4) {
                    v0 += bias[col]; v1 += bias[col+1];
                }
                float2 o;
                if (EPI == 1) { o.x = gelu_f(v0); o.y = gelu_f(v1); }
                else if (EPI == 3 || EPI == 5) {
                    float2 pv = *(float2*)(crow + col);
                    o.x = pv.x + v0*gmul; o.y = pv.y + v1*gmul;
                } else if (EPI == 4) { o.x = v0*gmul; o.y = v1*gmul; }
                else { o.x = v0; o.y = v1; }
                *(float2*)(crow + col) = o;
            }
        }
    }
}

// ---------------- host dispatch ----------------
static void set_smem_attrs() {
    static int done = 0;
    if (done) return;
    cudaFuncSetAttribute(mma_gemm<0>, cudaFuncAttributeMaxDynamicSharedMemorySize, SMEM_DYN);
    cudaFuncSetAttribute(mma_gemm<1>, cudaFuncAttributeMaxDynamicSharedMemorySize, SMEM_DYN);
    cudaFuncSetAttribute(mma_gemm<2>, cudaFuncAttributeMaxDynamicSharedMemorySize, SMEM_DYN);
    cudaFuncSetAttribute(mma_gemm<3>, cudaFuncAttributeMaxDynamicSharedMemorySize, SMEM_DYN);
    cudaFuncSetAttribute(mma_gemm<4>, cudaFuncAttributeMaxDynamicSharedMemorySize, SMEM_DYN);
    cudaFuncSetAttribute(mma_gemm<5>, cudaFuncAttributeMaxDynamicSharedMemorySize, SMEM_DYN);
    done = 1;
}

static void gemm(int epi, const float* A, const float* B, float* C, const float* bias,
                 int M, int N, int K, int lda, int ldb, int ldc,
                 int batch = 1, long sA = 0, long sB = 0, long sC = 0, int eid = 0) {
    dim3 grid(N/128, (M+127)/128, batch);
    dim3 blk(128);
    switch (epi) {
        case 0: mma_gemm<0><<<grid,blk,SMEM_DYN>>>(A,B,C,bias,M,N,K,lda,ldb,ldc,sA,sB,sC,eid); break;
        case 1: mma_gemm<1><<<grid,blk,SMEM_DYN>>>(A,B,C,bias,M,N,K,lda,ldb,ldc,sA,sB,sC,eid); break;
        case 2: mma_gemm<2><<<grid,blk,SMEM_DYN>>>(A,B,C,bias,M,N,K,lda,ldb,ldc,sA,sB,sC,eid); break;
        case 3: mma_gemm<3><<<grid,blk,SMEM_DYN>>>(A,B,C,bias,M,N,K,lda,ldb,ldc,sA,sB,sC,eid); break;
        case 4: mma_gemm<4><<<grid,blk,SMEM_DYN>>>(A,B,C,bias,M,N,K,lda,ldb,ldc,sA,sB,sC,eid); break;
        case 5: mma_gemm<5><<<grid,blk,SMEM_DYN>>>(A,B,C,bias,M,N,K,lda,ldb,ldc,sA,sB,sC,eid); break;
    }
}

static void transpose(const float* in, float* out, int R, int C, int batch = 1) {
    dim3 grid((C+31)/32, (R+31)/32, batch);
    transpose_k<<<grid, dim3(32,8)>>>(in, out, R, C);
}

extern "C" void kernel_launch(void* const* d_in, const int* in_sizes, int n_in,
                              void* d_out, int out_size) {
    const float* x   = (const float*)d_in[0];
    const float* sw1 = (const float*)d_in[1];  const float* sb1 = (const float*)d_in[2];
    const float* sw2 = (const float*)d_in[3];  const float* sb2 = (const float*)d_in[4];
    const float* gw  = (const float*)d_in[5];  const float* gb  = (const float*)d_in[6];
    const float* rw  = (const float*)d_in[7];  const float* rb  = (const float*)d_in[8];
    const float* ck  = (const float*)d_in[9];
    const float* cw1 = (const float*)d_in[10]; const float* cb1 = (const float*)d_in[11];
    const float* cw2 = (const float*)d_in[12]; const float* cb2 = (const float*)d_in[13];
    const float* fw1 = (const float*)d_in[14]; const float* fb1 = (const float*)d_in[15];
    const float* fw2 = (const float*)d_in[16]; const float* fb2 = (const float*)d_in[17];
    const float* mw1 = (const float*)d_in[18]; const float* mb1 = (const float*)d_in[19];
    const float* mw2 = (const float*)d_in[20]; const float* mb2 = (const float*)d_in[21];
    float* out = (float*)d_out;

    set_smem_attrs();

    void* p;
    cudaGetSymbolAddress(&p, g_H);    float* H    = (float*)p;
    cudaGetSymbolAddress(&p, g_xc);   float* xc   = (float*)p;
    cudaGetSymbolAddress(&p, g_xT);   float* xT   = (float*)p;
    cudaGetSymbolAddress(&p, g_cat);  float* cat  = (float*)p;
    cudaGetSymbolAddress(&p, g_fo);   float* fo   = (float*)p;
    cudaGetSymbolAddress(&p, g_foT);  float* foT  = (float*)p;
    cudaGetSymbolAddress(&p, g_CiSi); float* CiSi = (float*)p;
    cudaGetSymbolAddress(&p, g_Acos); float* Acos = (float*)p;
    cudaGetSymbolAddress(&p, g_Asin); float* Asin = (float*)p;
    cudaGetSymbolAddress(&p, g_WT);   float* WT   = (float*)p;

    const long M1 = 1048576L;
    float* sw1T = WT;
    float* sw2T = WT + 2*M1;
    float* mw1T = WT + 4*M1;
    float* mw2T = WT + 8*M1;
    float* cw1T = WT + 12*M1;
    float* cw2T = WT + 16*M1;
    float* fw1T = WT + 20*M1;
    float* fw2T = WT + 28*M1;

    const long NEL = (long)NTOK*DD;
    const int EW_BLOCKS = (int)((NEL + 255) / 256);

    // Launch order arranged so launch #6 (index 5) is the flagship EPI1 GEMM
    // (ncu capture is -s 5 -c 1).
    init_fwd<<<(NF*TT + 255)/256, 256>>>();                       // 0
    init_inv<<<(int)(((long)TT*KI + 255)/256), 256>>>();          // 1
    router_kernel<<<NTOK, 256>>>(x, rw, rb, gw, gb);              // 2
    aux_kernel<<<1, 256>>>(out, out_size);                        // 3
    transpose(sw1, sw1T, DD, FFD);                                // 4
    gemm(1, x, sw1T, H,   sb1, NTOK, FFD, DD,  DD,  DD,  FFD);    // 5  <-- PROFILED
    transpose(sw2, sw2T, FFD, DD);
    gemm(4, H, sw2T, out, sb2, NTOK, DD,  FFD, FFD, FFD, DD);

    // plain MLP experts (eid 2,5)
    transpose(mw1, mw1T, DD, FFD, 2);
    transpose(mw2, mw2T, FFD, DD, 2);
    for (int j = 0; j < 2; j++) {
        gemm(1, x, mw1T + (long)j*2*M1, H,   mb1 + j*FFD, NTOK, FFD, DD,  DD,  DD,  FFD);
        gemm(3, H, mw2T + (long)j*2*M1, out, mb2 + j*DD,  NTOK, DD,  FFD, FFD, FFD, DD, 1,0,0,0, j==0?2:5);
    }

    // conv experts (eid 0,3)
    transpose(cw1, cw1T, DD, FFD, 2);
    transpose(cw2, cw2T, FFD, DD, 2);
    for (int j = 0; j < 2; j++) {
        conv_kernel<<<EW_BLOCKS, 256>>>(x, ck + (long)j*DD*3, xc);
        gemm(1, xc, cw1T + (long)j*2*M1, H,   cb1 + j*FFD, NTOK, FFD, DD,  DD,  DD,  FFD);
        gemm(3, H,  cw2T + (long)j*2*M1, out, cb2 + j*DD,  NTOK, DD,  FFD, FFD, FFD, DD, 1,0,0,0, j==0?0:3);
    }

    // fourier experts (eid 1,4)
    transpose(fw1, fw1T, 2048, FFD, 2);
    transpose(fw2, fw2T, FFD, 2048, 2);
    transpose(x, xT, TT, DD, BSZ);
    gemm(0, Acos, xT, cat,        nullptr, NF, DD, TT, TT, TT, 2048, BSZ, 0, (long)DD*TT, (long)NF*2048);
    gemm(0, Asin, xT, cat + 1024, nullptr, NF, DD, TT, TT, TT, 2048, BSZ, 0, (long)DD*TT, (long)NF*2048);
    for (int j = 0; j < 2; j++) {
        gemm(1, cat, fw1T + (long)j*4*M1, H,  fb1 + j*FFD,  BSZ*NF, FFD,  2048, 2048, 2048, FFD);
        gemm(2, H,   fw2T + (long)j*4*M1, fo, fb2 + j*2048, BSZ*NF, 2048, FFD,  FFD,  FFD,  2048);
        transpose_fo<<<dim3(33, 32, BSZ), dim3(32,8)>>>(fo, foT, 0, 0);
        transpose_fo<<<dim3(33, 32, BSZ), dim3(32,8)>>>(fo, foT, 1024, NFP);
        gemm(5, CiSi, foT, out, nullptr, TT, DD, KI, KI, KI, DD, BSZ, 0, (long)DD*KI, (long)TT*DD, j==0?1:4);
    }
}

// round 14
// speedup vs baseline: 1.4993x; 1.4993x over previous
#include <cuda_runtime.h>
#include <math.h>

#define BSZ 8
#define TT  2048
#define DD  1024
#define FFD 2048
#define EE  6
#define NTOK (BSZ*TT)
#define NF  1025
#define NFP 1056
#define KI  (2*NFP)

typedef unsigned int u32;
typedef unsigned long long u64;

// ---------------- scratch ----------------
__device__ float g_gate[NTOK*EE];
__device__ float g_gsh[NTOK];
__device__ float g_probs[NTOK*EE];
__device__ int   g_idx[NTOK*2];
__device__ float g_H[NTOK*(long)FFD];
__device__ float g_xc[NTOK*(long)DD];
__device__ float g_xr[NTOK*(long)DD];
__device__ float g_xT[BSZ*(long)DD*TT];
__device__ float g_cat[BSZ*(long)NF*2048];
__device__ float g_fo[BSZ*(long)NF*2048];
__device__ float g_foT[BSZ*(long)DD*KI];
__device__ float g_CiSi[(long)TT*KI];
__device__ float g_Acos[(long)NF*TT];
__device__ float g_Asin[(long)NF*TT];
__device__ float g_WT[36u*1024u*1024u];

// ---------------- tf32 rounding helpers ----------------
__device__ __forceinline__ u32 tf32r(float f) {
    u32 r; asm("cvt.rna.tf32.f32 %0, %1;" : "=r"(r) : "f"(f)); return r;
}
__device__ __forceinline__ float tf32f(float f) {
    return __uint_as_float(tf32r(f));
}

// ---------------- init: DFT bases (tf32-rounded at rest) ----------------
__global__ void init_fwd() {
    int i = blockIdx.x*blockDim.x + threadIdx.x;
    if (i >= NF*TT) return;
    int k = i / TT, t = i % TT;
    int idx = (k*t) & (TT-1);
    float fr = (float)idx / (float)(TT/2);
    g_Acos[i] = tf32f(cospif(fr));
    g_Asin[i] = tf32f(-sinpif(fr));
}
__global__ void init_inv() {
    long i = (long)blockIdx.x*blockDim.x + threadIdx.x;
    if (i >= (long)TT*KI) return;
    int t = (int)(i / KI), kk = (int)(i % KI);
    int isimag = kk >= NFP;
    int k = isimag ? kk - NFP : kk;
    float v = 0.f;
    const float invT = 1.0f/(float)TT;
    if (k < NF) {
        int idx = (k*t) & (TT-1);
        float fr = (float)idx / (float)(TT/2);
        if (!isimag) {
            if (k == 0) v = invT;
            else if (k == TT/2) v = ((t & 1) ? -invT : invT);
            else v = 2.0f*cospif(fr)*invT;
        } else {
            if (k != 0 && k != TT/2) v = -2.0f*sinpif(fr)*invT;
        }
    }
    g_CiSi[i] = tf32f(v);
}

// ---------------- router + gates (raw x) ----------------
__global__ void router_kernel(const float* __restrict__ x,
                              const float* __restrict__ rw, const float* __restrict__ rb,
                              const float* __restrict__ gw, const float* __restrict__ gb) {
    __shared__ float sx[DD];
    __shared__ float slog[8];
    int tok = blockIdx.x;
    const float* xr = x + (long)tok * DD;
    for (int i = threadIdx.x; i < DD; i += blockDim.x) sx[i] = xr[i];
    __syncthreads();
    int w = threadIdx.x >> 5, lane = threadIdx.x & 31;
    if (w < 7) {
        float acc = 0.f;
        if (w < 6) { for (int i = lane; i < DD; i += 32) acc += sx[i] * rw[i*EE + w]; }
        else       { for (int i = lane; i < DD; i += 32) acc += sx[i] * gw[i]; }
        #pragma unroll
        for (int o = 16; o > 0; o >>= 1) acc += __shfl_down_sync(0xffffffffu, acc, o);
        if (lane == 0) slog[w] = acc + (w < 6 ? rb[w] : gb[0]);
    }
    __syncthreads();
    if (threadIdx.x == 0) {
        float l[EE], mx = -1e30f;
        for (int e = 0; e < EE; e++) { l[e] = slog[e]; mx = fmaxf(mx, l[e]); }
        float den = 0.f;
        for (int e = 0; e < EE; e++) { l[e] = expf(l[e]-mx); den += l[e]; }
        float p[EE];
        for (int e = 0; e < EE; e++) { p[e] = l[e]/den; g_probs[tok*EE+e] = p[e]; g_gate[tok*EE+e] = 0.f; }
        int i1 = 0; for (int e = 1; e < EE; e++) if (p[e] > p[i1]) i1 = e;
        int i2 = (i1==0)?1:0;
        for (int e = 0; e < EE; e++) if (e != i1 && p[e] > p[i2]) i2 = e;
        g_gate[tok*EE+i1] = p[i1];
        g_gate[tok*EE+i2] = p[i2];
        g_idx[tok*2]   = i1;
        g_idx[tok*2+1] = i2;
        g_gsh[tok] = 1.0f/(1.0f+expf(-slog[6]));
    }
}

__global__ void aux_kernel(float* __restrict__ out, int out_size) {
    __shared__ float sf[EE][256];
    __shared__ int   si[EE][256];
    float imp[EE]; int cnt[EE];
    for (int e = 0; e < EE; e++) { imp[e] = 0.f; cnt[e] = 0; }
    for (int n = threadIdx.x; n < NTOK; n += 256) {
        #pragma unroll
        for (int e = 0; e < EE; e++) imp[e] += g_probs[n*EE+e];
        cnt[g_idx[n*2]]++; cnt[g_idx[n*2+1]]++;
    }
    for (int e = 0; e < EE; e++) { sf[e][threadIdx.x] = imp[e]; si[e][threadIdx.x] = cnt[e]; }
    __syncthreads();
    for (int s = 128; s > 0; s >>= 1) {
        if (threadIdx.x < s)
            for (int e = 0; e < EE; e++) {
                sf[e][threadIdx.x] += sf[e][threadIdx.x+s];
                si[e][threadIdx.x] += si[e][threadIdx.x+s];
            }
        __syncthreads();
    }
    if (threadIdx.x == 0) {
        float aux = 0.f;
        for (int e = 0; e < EE; e++)
            aux += ((float)si[e][0] / (2.0f*(float)NTOK)) * (sf[e][0] / (float)NTOK);
        out[out_size-1] = (float)EE * aux;
    }
}

// ---------------- conv (raw x in, tf32-rounded xc out) ----------------
__global__ void conv_kernel(const float* __restrict__ x, const float* __restrict__ ck,
                            float* __restrict__ xc) {
    long i = (long)blockIdx.x*blockDim.x + threadIdx.x;
    if (i >= (long)NTOK*DD) return;
    int d = (int)(i % DD);
    long td = i / DD;
    int t = (int)(td % TT);
    float k0 = ck[d*3], k1 = ck[d*3+1], k2 = ck[d*3+2];
    float c = x[i]*k1;
    if (t > 0)     c += x[i-DD]*k0;
    if (t < TT-1)  c += x[i+DD]*k2;
    xc[i] = tf32f(x[i] + c);
}

// ---------------- rounded copy of x for GEMM A use ----------------
__global__ void round_copy(const float* __restrict__ in, float* __restrict__ out, long n) {
    long i = (long)blockIdx.x*blockDim.x + threadIdx.x;
    if (i < n) out[i] = tf32f(in[i]);
}

// ---------------- transposes (tf32-rounded outputs; GEMM-operands only) ----------------
__global__ void transpose_k(const float* __restrict__ in, float* __restrict__ out,
                            int R, int C) {
    __shared__ float t[32][33];
    long bo = (long)blockIdx.z * R * C;
    in += bo; out += bo;
    int c0 = blockIdx.x*32, r0 = blockIdx.y*32;
    #pragma unroll
    for (int i = 0; i < 4; i++) {
        int r = r0 + threadIdx.y + i*8, c = c0 + threadIdx.x;
        t[threadIdx.y+i*8][threadIdx.x] = (r < R && c < C) ? in[(long)r*C + c] : 0.f;
    }
    __syncthreads();
    #pragma unroll
    for (int i = 0; i < 4; i++) {
        int c = c0 + threadIdx.y + i*8, r = r0 + threadIdx.x;
        if (c < C && r < R) out[(long)c*R + r] = tf32f(t[threadIdx.x][threadIdx.y+i*8]);
    }
}

__global__ void transpose_fo(const float* __restrict__ fo, float* __restrict__ foT,
                             int coloff, int kbase) {
    __shared__ float t[32][33];
    int b = blockIdx.z;
    const float* in = fo + (long)b*NF*2048;
    float* ob = foT + (long)b*DD*KI;
    int k0 = blockIdx.x*32, d0 = blockIdx.y*32;
    #pragma unroll
    for (int i = 0; i < 4; i++) {
        int k = k0 + threadIdx.y + i*8;
        t[threadIdx.y+i*8][threadIdx.x] = (k < NF) ? in[(long)k*2048 + coloff + d0 + threadIdx.x] : 0.f;
    }
    __syncthreads();
    #pragma unroll
    for (int i = 0; i < 4; i++) {
        int d = d0 + threadIdx.y + i*8;
        ob[(long)d*KI + kbase + k0 + threadIdx.x] = tf32f(t[threadIdx.x][threadIdx.y+i*8]);
    }
}

// ================= tf32 mma.sync GEMM (operands pre-rounded; no CVT in loop) =================
// D[M,N] = A[M,K] @ Bt[N,K]^T; A,Bt K-major tf32-at-rest. K%16==0, N%128==0, M ragged OK.
#define SPAD 20
#define NSTAGE 3
#define TILE_FLOATS (128*SPAD)
#define SMEM_DYN (NSTAGE*2*TILE_FLOATS*4)

__device__ __forceinline__ float gelu_f(float v) {
    return 0.5f*v*(1.0f + erff(v*0.7071067811865475f));
}
__device__ __forceinline__ void cp16(u32 dst, const void* src, int sz) {
    asm volatile("cp.async.ca.shared.global [%0], [%1], 16, %2;" :: "r"(dst), "l"(src), "r"(sz));
}
__device__ __forceinline__ void mma8(float* c, const u32* a, const u32* b) {
    asm volatile("mma.sync.aligned.m16n8k8.row.col.f32.tf32.tf32.f32 "
        "{%0,%1,%2,%3}, {%4,%5,%6,%7}, {%8,%9}, {%0,%1,%2,%3};"
        : "+f"(c[0]), "+f"(c[1]), "+f"(c[2]), "+f"(c[3])
        : "r"(a[0]), "r"(a[1]), "r"(a[2]), "r"(a[3]), "r"(b[0]), "r"(b[1]));
}

// EPI: 0 tf32(v) store, 1 tf32(gelu(v+b)) store, 2 tf32(v+b) store,
//      3 out+=(v+b)*gate[r,eid], 4 out=(v+b)*gsh[r], 5 out += v*gate[z*TT+r, eid]
template<int EPI>
__global__ void __launch_bounds__(256, 2)
mma_gemm(const float* __restrict__ A, const float* __restrict__ B,
         float* __restrict__ C, const float* __restrict__ bias,
         int M, int N, int K, int lda, int ldb, int ldc,
         long sA, long sB, long sC, int eid)
{
    extern __shared__ float smp[];
    float* Asm = smp;
    float* Bsm = smp + NSTAGE*TILE_FLOATS;
    A += (long)blockIdx.z * sA;
    B += (long)blockIdx.z * sB;
    C += (long)blockIdx.z * sC;
    const int row0 = blockIdx.y * 128, col0 = blockIdx.x * 128;
    const int tid = threadIdx.x, lane = tid & 31, wid = tid >> 5;
    const int wm = (wid >> 2) * 64, wn = (wid & 3) * 32;
    const u32 sa = (u32)__cvta_generic_to_shared(Asm);
    const u32 sb = (u32)__cvta_generic_to_shared(Bsm);
    const int g4 = lane >> 2, q4 = lane & 3;

    float acc[4][4][4];
    #pragma unroll
    for (int mi = 0; mi < 4; mi++)
        #pragma unroll
        for (int ni = 0; ni < 4; ni++)
            #pragma unroll
            for (int q = 0; q < 4; q++) acc[mi][ni][q] = 0.f;

    const int ldrow = tid >> 2, ldq = tid & 3;
    const int nk = K / 16;

    auto loadStage = [&](int ic, int buf) {
        int k0 = ic * 16;
        #pragma unroll
        for (int i = 0; i < 2; i++) {
            int row = ldrow + i*64;
            int gm = row0 + row;
            bool ok = gm < M;
            const float* srcA = A + (ok ? ((long)gm*lda + k0 + ldq*4) : 0);
            cp16(sa + (u32)(((buf*128 + row)*SPAD + ldq*4)*4), srcA, ok ? 16 : 0);
            const float* srcB = B + (long)(col0 + row)*ldb + k0 + ldq*4;
            cp16(sb + (u32)(((buf*128 + row)*SPAD + ldq*4)*4), srcB, 16);
        }
        asm volatile("cp.async.commit_group;" ::: "memory");
    };

    loadStage(0, 0);
    if (nk > 1) loadStage(1, 1);

    int buf = 0;
    for (int ic = 0; ic < nk; ic++) {
        asm volatile("cp.async.wait_group 1;" ::: "memory");
        __syncthreads();
        if (ic + 2 < nk) loadStage(ic + 2, (ic + 2) % NSTAGE);

        const float* Ab = Asm + buf*TILE_FLOATS;
        const float* Bb = Bsm + buf*TILE_FLOATS;
        #pragma unroll
        for (int ks = 0; ks < 2; ks++) {
            u32 areg[4][4], breg[4][2];
            #pragma unroll
            for (int mi = 0; mi < 4; mi++) {
                const float* ap = Ab + (wm + mi*16 + g4)*SPAD + ks*8 + q4;
                areg[mi][0] = __float_as_uint(ap[0]);
                areg[mi][1] = __float_as_uint(ap[8*SPAD]);
                areg[mi][2] = __float_as_uint(ap[4]);
                areg[mi][3] = __float_as_uint(ap[8*SPAD + 4]);
            }
            #pragma unroll
            for (int ni = 0; ni < 4; ni++) {
                const float* bp = Bb + (wn + ni*8 + g4)*SPAD + ks*8 + q4;
                breg[ni][0] = __float_as_uint(bp[0]);
                breg[ni][1] = __float_as_uint(bp[4]);
            }
            #pragma unroll
            for (int mi = 0; mi < 4; mi++)
                #pragma unroll
                for (int ni = 0; ni < 4; ni++)
                    mma8(acc[mi][ni], areg[mi], breg[ni]);
        }
        buf = (buf + 1 == NSTAGE) ? 0 : buf + 1;
    }

    // ---- epilogue (C frag: rows g4 / g4+8, cols 2*q4, 2*q4+1) ----
    #pragma unroll
    for (int mi = 0; mi < 4; mi++) {
        #pragma unroll
        for (int h = 0; h < 2; h++) {
            int r = row0 + wm + mi*16 + g4 + h*8;
            if (r >= M) continue;
            float gmul = 1.f;
            if (EPI == 3) gmul = g_gate[(long)r*EE + eid];
            if (EPI == 4) gmul = g_gsh[r];
            if (EPI == 5) gmul = g_gate[((long)blockIdx.z*TT + r)*EE + eid];
            float* crow = C + (long)r*ldc;
            #pragma unroll
            for (int ni = 0; ni < 4; ni++) {
                int col = col0 + wn + ni*8 + 2*q4;
                float v0 = acc[mi][ni][h*2 + 0];
                float v1 = acc[mi][ni][h*2 + 1];
                if (EPI == 1 || EPI == 2 || EPI == 3 || EPI == 4) {
                    v0 += bias[col]; v1 += bias[col+1];
                }
                float2 o;
                if (EPI == 0)      { o.x = tf32f(v0); o.y = tf32f(v1); }
                else if (EPI == 1) { o.x = tf32f(gelu_f(v0)); o.y = tf32f(gelu_f(v1)); }
                else if (EPI == 2) { o.x = tf32f(v0); o.y = tf32f(v1); }
                else if (EPI == 3 || EPI == 5) {
                    float2 pv = *(float2*)(crow + col);
                    o.x = pv.x + v0*gmul; o.y = pv.y + v1*gmul;
                } else { o.x = v0*gmul; o.y = v1*gmul; }
                *(float2*)(crow + col) = o;
            }
        }
    }
}

// ---------------- host dispatch ----------------
static void set_smem_attrs() {
    static int done = 0;
    if (done) return;
    cudaFuncSetAttribute(mma_gemm<0>, cudaFuncAttributeMaxDynamicSharedMemorySize, SMEM_DYN);
    cudaFuncSetAttribute(mma_gemm<1>, cudaFuncAttributeMaxDynamicSharedMemorySize, SMEM_DYN);
    cudaFuncSetAttribute(mma_gemm<2>, cudaFuncAttributeMaxDynamicSharedMemorySize, SMEM_DYN);
    cudaFuncSetAttribute(mma_gemm<3>, cudaFuncAttributeMaxDynamicSharedMemorySize, SMEM_DYN);
    cudaFuncSetAttribute(mma_gemm<4>, cudaFuncAttributeMaxDynamicSharedMemorySize, SMEM_DYN);
    cudaFuncSetAttribute(mma_gemm<5>, cudaFuncAttributeMaxDynamicSharedMemorySize, SMEM_DYN);
    done = 1;
}

static void gemm(int epi, const float* A, const float* B, float* C, const float* bias,
                 int M, int N, int K, int lda, int ldb, int ldc,
                 int batch = 1, long sA = 0, long sB = 0, long sC = 0, int eid = 0) {
    dim3 grid(N/128, (M+127)/128, batch);
    dim3 blk(256);
    switch (epi) {
        case 0: mma_gemm<0><<<grid,blk,SMEM_DYN>>>(A,B,C,bias,M,N,K,lda,ldb,ldc,sA,sB,sC,eid); break;
        case 1: mma_gemm<1><<<grid,blk,SMEM_DYN>>>(A,B,C,bias,M,N,K,lda,ldb,ldc,sA,sB,sC,eid); break;
        case 2: mma_gemm<2><<<grid,blk,SMEM_DYN>>>(A,B,C,bias,M,N,K,lda,ldb,ldc,sA,sB,sC,eid); break;
        case 3: mma_gemm<3><<<grid,blk,SMEM_DYN>>>(A,B,C,bias,M,N,K,lda,ldb,ldc,sA,sB,sC,eid); break;
        case 4: mma_gemm<4><<<grid,blk,SMEM_DYN>>>(A,B,C,bias,M,N,K,lda,ldb,ldc,sA,sB,sC,eid); break;
        case 5: mma_gemm<5><<<grid,blk,SMEM_DYN>>>(A,B,C,bias,M,N,K,lda,ldb,ldc,sA,sB,sC,eid); break;
    }
}

static void transpose(const float* in, float* out, int R, int C, int batch = 1) {
    dim3 grid((C+31)/32, (R+31)/32, batch);
    transpose_k<<<grid, dim3(32,8)>>>(in, out, R, C);
}

extern "C" void kernel_launch(void* const* d_in, const int* in_sizes, int n_in,
                              void* d_out, int out_size) {
    const float* x   = (const float*)d_in[0];
    const float* sw1 = (const float*)d_in[1];  const float* sb1 = (const float*)d_in[2];
    const float* sw2 = (const float*)d_in[3];  const float* sb2 = (const float*)d_in[4];
    const float* gw  = (const float*)d_in[5];  const float* gb  = (const float*)d_in[6];
    const float* rw  = (const float*)d_in[7];  const float* rb  = (const float*)d_in[8];
    const float* ck  = (const float*)d_in[9];
    const float* cw1 = (const float*)d_in[10]; const float* cb1 = (const float*)d_in[11];
    const float* cw2 = (const float*)d_in[12]; const float* cb2 = (const float*)d_in[13];
    const float* fw1 = (const float*)d_in[14]; const float* fb1 = (const float*)d_in[15];
    const float* fw2 = (const float*)d_in[16]; const float* fb2 = (const float*)d_in[17];
    const float* mw1 = (const float*)d_in[18]; const float* mb1 = (const float*)d_in[19];
    const float* mw2 = (const float*)d_in[20]; const float* mb2 = (const float*)d_in[21];
    float* out = (float*)d_out;

    set_smem_attrs();

    void* p;
    cudaGetSymbolAddress(&p, g_H);    float* H    = (float*)p;
    cudaGetSymbolAddress(&p, g_xc);   float* xc   = (float*)p;
    cudaGetSymbolAddress(&p, g_xr);   float* xr   = (float*)p;
    cudaGetSymbolAddress(&p, g_xT);   float* xT   = (float*)p;
    cudaGetSymbolAddress(&p, g_cat);  float* cat  = (float*)p;
    cudaGetSymbolAddress(&p, g_fo);   float* fo   = (float*)p;
    cudaGetSymbolAddress(&p, g_foT);  float* foT  = (float*)p;
    cudaGetSymbolAddress(&p, g_CiSi); float* CiSi = (float*)p;
    cudaGetSymbolAddress(&p, g_Acos); float* Acos = (float*)p;
    cudaGetSymbolAddress(&p, g_Asin); float* Asin = (float*)p;
    cudaGetSymbolAddress(&p, g_WT);   float* WT   = (float*)p;

    const long M1 = 1048576L;
    float* sw1T = WT;
    float* sw2T = WT + 2*M1;
    float* mw1T = WT + 4*M1;
    float* mw2T = WT + 8*M1;
    float* cw1T = WT + 12*M1;
    float* cw2T = WT + 16*M1;
    float* fw1T = WT + 20*M1;
    float* fw2T = WT + 28*M1;

    const long NEL = (long)NTOK*DD;
    const int EW_BLOCKS = (int)((NEL + 255) / 256);

    init_fwd<<<(NF*TT + 255)/256, 256>>>();
    init_inv<<<(int)(((long)TT*KI + 255)/256), 256>>>();
    router_kernel<<<NTOK, 256>>>(x, rw, rb, gw, gb);
    aux_kernel<<<1, 256>>>(out, out_size);
    round_copy<<<EW_BLOCKS, 256>>>(x, xr, NEL);

    transpose(sw1, sw1T, DD, FFD);
    gemm(1, xr, sw1T, H,   sb1, NTOK, FFD, DD,  DD,  DD,  FFD);
    transpose(sw2, sw2T, FFD, DD);
    gemm(4, H, sw2T, out, sb2, NTOK, DD,  FFD, FFD, FFD, DD);

    // plain MLP experts (eid 2,5)
    transpose(mw1, mw1T, DD, FFD, 2);
    transpose(mw2, mw2T, FFD, DD, 2);
    for (int j = 0; j < 2; j++) {
        gemm(1, xr, mw1T + (long)j*2*M1, H,   mb1 + j*FFD, NTOK, FFD, DD,  DD,  DD,  FFD);
        gemm(3, H,  mw2T + (long)j*2*M1, out, mb2 + j*DD,  NTOK, DD,  FFD, FFD, FFD, DD, 1,0,0,0, j==0?2:5);
    }

    // conv experts (eid 0,3)
    transpose(cw1, cw1T, DD, FFD, 2);
    transpose(cw2, cw2T, FFD, DD, 2);
    for (int j = 0; j < 2; j++) {
        conv_kernel<<<EW_BLOCKS, 256>>>(x, ck + (long)j*DD*3, xc);
        gemm(1, xc, cw1T + (long)j*2*M1, H,   cb1 + j*FFD, NTOK, FFD, DD,  DD,  DD,  FFD);
        gemm(3, H,  cw2T + (long)j*2*M1, out, cb2 + j*DD,  NTOK, DD,  FFD, FFD, FFD, DD, 1,0,0,0, j==0?0:3);
    }

    // fourier experts (eid 1,4)
    transpose(fw1, fw1T, 2048, FFD, 2);
    transpose(fw2, fw2T, FFD, 2048, 2);
    transpose(x, xT, TT, DD, BSZ);
    gemm(0, Acos, xT, cat,        nullptr, NF, DD, TT, TT, TT, 2048, BSZ, 0, (long)DD*TT, (long)NF*2048);
    gemm(0, Asin, xT, cat + 1024, nullptr, NF, DD, TT, TT, TT, 2048, BSZ, 0, (long)DD*TT, (long)NF*2048);
    for (int j = 0; j < 2; j++) {
        gemm(1, cat, fw1T + (long)j*4*M1, H,  fb1 + j*FFD,  BSZ*NF, FFD,  2048, 2048, 2048, FFD);
        gemm(2, H,   fw2T + (long)j*4*M1, fo, fb2 + j*2048, BSZ*NF, 2048, FFD,  FFD,  FFD,  2048);
        transpose_fo<<<dim3(33, 32, BSZ), dim3(32,8)>>>(fo, foT, 0, 0);
        transpose_fo<<<dim3(33, 32, BSZ), dim3(32,8)>>>(fo, foT, 1024, NFP);
        gemm(5, CiSi, foT, out, nullptr, TT, DD, KI, KI, KI, DD, BSZ, 0, (long)DD*KI, (long)TT*DD, j==0?1:4);
    }
}

// round 15
// speedup vs baseline: 2.2158x; 1.4779x over previous
#include <cuda_runtime.h>
#include <math.h>

#define BSZ 8
#define TT  2048
#define DD  1024
#define FFD 2048
#define EE  6
#define NTOK (BSZ*TT)
#define NF  1025
#define NFP 1056
#define KI  (2*NFP)

typedef unsigned int u32;
typedef unsigned long long u64;

// ---------------- scratch ----------------
__device__ float g_gate[NTOK*EE];
__device__ float g_gsh[NTOK];
__device__ float g_probs[NTOK*EE];
__device__ int   g_idx[NTOK*2];
__device__ int   g_cnt[EE];
__device__ int   g_list[EE*NTOK];
__device__ int   g_cntb[2*BSZ];
__device__ int   g_listb[2*BSZ*TT];
__device__ float g_H[NTOK*(long)FFD];
__device__ float g_xc[NTOK*(long)DD];
__device__ float g_xr[NTOK*(long)DD];
__device__ float g_xT[BSZ*(long)DD*TT];
__device__ float g_cat[BSZ*(long)NF*2048];
__device__ float g_fo[BSZ*(long)NF*2048];
__device__ float g_foT[BSZ*(long)DD*KI];
__device__ float g_CiSi[(long)TT*KI];
__device__ float g_Acos[(long)NF*TT];
__device__ float g_Asin[(long)NF*TT];
__device__ float g_WT[36u*1024u*1024u];

// ---------------- tf32 rounding helpers ----------------
__device__ __forceinline__ u32 tf32r(float f) {
    u32 r; asm("cvt.rna.tf32.f32 %0, %1;" : "=r"(r) : "f"(f)); return r;
}
__device__ __forceinline__ float tf32f(float f) {
    return __uint_as_float(tf32r(f));
}

// ---------------- init: DFT bases (tf32 at rest) ----------------
__global__ void init_fwd() {
    int i = blockIdx.x*blockDim.x + threadIdx.x;
    if (i >= NF*TT) return;
    int k = i / TT, t = i % TT;
    int idx = (k*t) & (TT-1);
    float fr = (float)idx / (float)(TT/2);
    g_Acos[i] = tf32f(cospif(fr));
    g_Asin[i] = tf32f(-sinpif(fr));
}
__global__ void init_inv() {
    long i = (long)blockIdx.x*blockDim.x + threadIdx.x;
    if (i >= (long)TT*KI) return;
    int t = (int)(i / KI), kk = (int)(i % KI);
    int isimag = kk >= NFP;
    int k = isimag ? kk - NFP : kk;
    float v = 0.f;
    const float invT = 1.0f/(float)TT;
    if (k < NF) {
        int idx = (k*t) & (TT-1);
        float fr = (float)idx / (float)(TT/2);
        if (!isimag) {
            if (k == 0) v = invT;
            else if (k == TT/2) v = ((t & 1) ? -invT : invT);
            else v = 2.0f*cospif(fr)*invT;
        } else {
            if (k != 0 && k != TT/2) v = -2.0f*sinpif(fr)*invT;
        }
    }
    g_CiSi[i] = tf32f(v);
}

// ---------------- router + gates ----------------
__global__ void router_kernel(const float* __restrict__ x,
                              const float* __restrict__ rw, const float* __restrict__ rb,
                              const float* __restrict__ gw, const float* __restrict__ gb) {
    __shared__ float sx[DD];
    __shared__ float slog[8];
    int tok = blockIdx.x;
    const float* xr = x + (long)tok * DD;
    for (int i = threadIdx.x; i < DD; i += blockDim.x) sx[i] = xr[i];
    __syncthreads();
    int w = threadIdx.x >> 5, lane = threadIdx.x & 31;
    if (w < 7) {
        float acc = 0.f;
        if (w < 6) { for (int i = lane; i < DD; i += 32) acc += sx[i] * rw[i*EE + w]; }
        else       { for (int i = lane; i < DD; i += 32) acc += sx[i] * gw[i]; }
        #pragma unroll
        for (int o = 16; o > 0; o >>= 1) acc += __shfl_down_sync(0xffffffffu, acc, o);
        if (lane == 0) slog[w] = acc + (w < 6 ? rb[w] : gb[0]);
    }
    __syncthreads();
    if (threadIdx.x == 0) {
        float l[EE], mx = -1e30f;
        for (int e = 0; e < EE; e++) { l[e] = slog[e]; mx = fmaxf(mx, l[e]); }
        float den = 0.f;
        for (int e = 0; e < EE; e++) { l[e] = expf(l[e]-mx); den += l[e]; }
        float p[EE];
        for (int e = 0; e < EE; e++) { p[e] = l[e]/den; g_probs[tok*EE+e] = p[e]; g_gate[tok*EE+e] = 0.f; }
        int i1 = 0; for (int e = 1; e < EE; e++) if (p[e] > p[i1]) i1 = e;
        int i2 = (i1==0)?1:0;
        for (int e = 0; e < EE; e++) if (e != i1 && p[e] > p[i2]) i2 = e;
        g_gate[tok*EE+i1] = p[i1];
        g_gate[tok*EE+i2] = p[i2];
        g_idx[tok*2]   = i1;
        g_idx[tok*2+1] = i2;
        g_gsh[tok] = 1.0f/(1.0f+expf(-slog[6]));
    }
}

__global__ void zero_cnt() {
    if (threadIdx.x < EE) g_cnt[threadIdx.x] = 0;
    if (threadIdx.x < 2*BSZ) g_cntb[threadIdx.x] = 0;
}

__global__ void build_lists() {
    int n = blockIdx.x*blockDim.x + threadIdx.x;
    if (n >= NTOK) return;
    int b = n / TT, t = n % TT;
    #pragma unroll
    for (int s = 0; s < 2; s++) {
        int e = g_idx[n*2+s];
        int pos = atomicAdd(&g_cnt[e], 1);
        g_list[e*NTOK + pos] = n;
        if (e == 1 || e == 4) {
            int fj = (e == 1) ? 0 : 1;
            int pos2 = atomicAdd(&g_cntb[fj*BSZ + b], 1);
            g_listb[(fj*BSZ + b)*TT + pos2] = t;
        }
    }
}

__global__ void aux_kernel(float* __restrict__ out, int out_size) {
    __shared__ float sf[EE][256];
    __shared__ int   si[EE][256];
    float imp[EE]; int cnt[EE];
    for (int e = 0; e < EE; e++) { imp[e] = 0.f; cnt[e] = 0; }
    for (int n = threadIdx.x; n < NTOK; n += 256) {
        #pragma unroll
        for (int e = 0; e < EE; e++) imp[e] += g_probs[n*EE+e];
        cnt[g_idx[n*2]]++; cnt[g_idx[n*2+1]]++;
    }
    for (int e = 0; e < EE; e++) { sf[e][threadIdx.x] = imp[e]; si[e][threadIdx.x] = cnt[e]; }
    __syncthreads();
    for (int s = 128; s > 0; s >>= 1) {
        if (threadIdx.x < s)
            for (int e = 0; e < EE; e++) {
                sf[e][threadIdx.x] += sf[e][threadIdx.x+s];
                si[e][threadIdx.x] += si[e][threadIdx.x+s];
            }
        __syncthreads();
    }
    if (threadIdx.x == 0) {
        float aux = 0.f;
        for (int e = 0; e < EE; e++)
            aux += ((float)si[e][0] / (2.0f*(float)NTOK)) * (sf[e][0] / (float)NTOK);
        out[out_size-1] = (float)EE * aux;
    }
}

// ---------------- conv ----------------
__global__ void conv_kernel(const float* __restrict__ x, const float* __restrict__ ck,
                            float* __restrict__ xc) {
    long i = (long)blockIdx.x*blockDim.x + threadIdx.x;
    if (i >= (long)NTOK*DD) return;
    int d = (int)(i % DD);
    long td = i / DD;
    int t = (int)(td % TT);
    float k0 = ck[d*3], k1 = ck[d*3+1], k2 = ck[d*3+2];
    float c = x[i]*k1;
    if (t > 0)     c += x[i-DD]*k0;
    if (t < TT-1)  c += x[i+DD]*k2;
    xc[i] = tf32f(x[i] + c);
}

__global__ void round_copy(const float* __restrict__ in, float* __restrict__ out, long n) {
    long i = (long)blockIdx.x*blockDim.x + threadIdx.x;
    if (i < n) out[i] = tf32f(in[i]);
}

// ---------------- transposes (tf32 at rest) ----------------
__global__ void transpose_k(const float* __restrict__ in, float* __restrict__ out,
                            int R, int C) {
    __shared__ float t[32][33];
    long bo = (long)blockIdx.z * R * C;
    in += bo; out += bo;
    int c0 = blockIdx.x*32, r0 = blockIdx.y*32;
    #pragma unroll
    for (int i = 0; i < 4; i++) {
        int r = r0 + threadIdx.y + i*8, c = c0 + threadIdx.x;
        t[threadIdx.y+i*8][threadIdx.x] = (r < R && c < C) ? in[(long)r*C + c] : 0.f;
    }
    __syncthreads();
    #pragma unroll
    for (int i = 0; i < 4; i++) {
        int c = c0 + threadIdx.y + i*8, r = r0 + threadIdx.x;
        if (c < C && r < R) out[(long)c*R + r] = tf32f(t[threadIdx.x][threadIdx.y+i*8]);
    }
}

__global__ void transpose_fo(const float* __restrict__ fo, float* __restrict__ foT,
                             int coloff, int kbase) {
    __shared__ float t[32][33];
    int b = blockIdx.z;
    const float* in = fo + (long)b*NF*2048;
    float* ob = foT + (long)b*DD*KI;
    int k0 = blockIdx.x*32, d0 = blockIdx.y*32;
    #pragma unroll
    for (int i = 0; i < 4; i++) {
        int k = k0 + threadIdx.y + i*8;
        t[threadIdx.y+i*8][threadIdx.x] = (k < NF) ? in[(long)k*2048 + coloff + d0 + threadIdx.x] : 0.f;
    }
    __syncthreads();
    #pragma unroll
    for (int i = 0; i < 4; i++) {
        int d = d0 + threadIdx.y + i*8;
        ob[(long)d*KI + kbase + k0 + threadIdx.x] = tf32f(t[threadIdx.x][threadIdx.y+i*8]);
    }
}

// ================= tf32 mma.sync GEMM with gather/scatter sparsity =================
// D[M,N] = A[M,K] @ Bt[N,K]^T; operands tf32 at rest. K%16==0, N%128==0.
#define SPAD 20
#define NSTAGE 3
#define TILE_FLOATS (128*SPAD)
#define SMEM_DYN (NSTAGE*2*TILE_FLOATS*4)

__device__ __forceinline__ float gelu_f(float v) {
    return 0.5f*v*(1.0f + erff(v*0.7071067811865475f));
}
__device__ __forceinline__ void cp16(u32 dst, const void* src, int sz) {
    asm volatile("cp.async.ca.shared.global [%0], [%1], 16, %2;" :: "r"(dst), "l"(src), "r"(sz));
}
__device__ __forceinline__ void mma8(float* c, const u32* a, const u32* b) {
    asm volatile("mma.sync.aligned.m16n8k8.row.col.f32.tf32.tf32.f32 "
        "{%0,%1,%2,%3}, {%4,%5,%6,%7}, {%8,%9}, {%0,%1,%2,%3};"
        : "+f"(c[0]), "+f"(c[1]), "+f"(c[2]), "+f"(c[3])
        : "r"(a[0]), "r"(a[1]), "r"(a[2]), "r"(a[3]), "r"(b[0]), "r"(b[1]));
}

// EPI: 0 tf32(v) store, 1 tf32(gelu(v+b)) store, 2 tf32(v+b) store,
//      3 out[cr]+=(v+b)*gate[cr,eid], 4 out=(v+b)*gsh[r], 5 out[cr]+=v*gate[z*TT+cr,eid]
template<int EPI>
__global__ void __launch_bounds__(256, 2)
mma_gemm(const float* __restrict__ A, const float* __restrict__ B,
         float* __restrict__ C, const float* __restrict__ bias,
         int M, int N, int K, int lda, int ldb, int ldc,
         long sA, long sB, long sC, int eid,
         const int* __restrict__ gA, int gAstride,
         const int* __restrict__ sCi, int sCstride,
         const int* __restrict__ cntp, int cntZ)
{
    const int z = blockIdx.z;
    const int Meff = cntp ? cntp[cntZ ? z : 0] : M;
    const int row0 = blockIdx.y * 128;
    if (row0 >= Meff) return;
    extern __shared__ float smp[];
    float* Asm = smp;
    float* Bsm = smp + NSTAGE*TILE_FLOATS;
    A += (long)z * sA;
    B += (long)z * sB;
    C += (long)z * sC;
    const int col0 = blockIdx.x * 128;
    const int tid = threadIdx.x, lane = tid & 31, wid = tid >> 5;
    const int wm = (wid >> 2) * 64, wn = (wid & 3) * 32;
    const u32 sa = (u32)__cvta_generic_to_shared(Asm);
    const u32 sb = (u32)__cvta_generic_to_shared(Bsm);
    const int g4 = lane >> 2, q4 = lane & 3;
    const int* gAe = gA ? gA + (long)z*gAstride : (const int*)0;
    const int* sCe = sCi ? sCi + (long)z*sCstride : (const int*)0;

    float acc[4][4][4];
    #pragma unroll
    for (int mi = 0; mi < 4; mi++)
        #pragma unroll
        for (int ni = 0; ni < 4; ni++)
            #pragma unroll
            for (int q = 0; q < 4; q++) acc[mi][ni][q] = 0.f;

    const int ldrow = tid >> 2, ldq = tid & 3;
    const int nk = K / 16;

    // preload gather rows (invariant across stages)
    const int r0a = row0 + ldrow, r1a = row0 + ldrow + 64;
    const bool ok0 = r0a < Meff, ok1 = r1a < Meff;
    const long a0 = ok0 ? (long)(gAe ? gAe[r0a] : r0a)*lda : 0;
    const long a1 = ok1 ? (long)(gAe ? gAe[r1a] : r1a)*lda : 0;
    const long b0 = (long)(col0 + ldrow)*ldb;
    const long b1 = (long)(col0 + ldrow + 64)*ldb;

    auto loadStage = [&](int ic, int buf) {
        int k0 = ic * 16;
        cp16(sa + (u32)(((buf*128 + ldrow)*SPAD + ldq*4)*4),      A + a0 + k0 + ldq*4, ok0 ? 16 : 0);
        cp16(sa + (u32)(((buf*128 + ldrow + 64)*SPAD + ldq*4)*4), A + a1 + k0 + ldq*4, ok1 ? 16 : 0);
        cp16(sb + (u32)(((buf*128 + ldrow)*SPAD + ldq*4)*4),      B + b0 + k0 + ldq*4, 16);
        cp16(sb + (u32)(((buf*128 + ldrow + 64)*SPAD + ldq*4)*4), B + b1 + k0 + ldq*4, 16);
        asm volatile("cp.async.commit_group;" ::: "memory");
    };

    loadStage(0, 0);
    if (nk > 1) loadStage(1, 1);

    int buf = 0;
    for (int ic = 0; ic < nk; ic++) {
        asm volatile("cp.async.wait_group 1;" ::: "memory");
        __syncthreads();
        if (ic + 2 < nk) loadStage(ic + 2, (ic + 2) % NSTAGE);

        const float* Ab = Asm + buf*TILE_FLOATS;
        const float* Bb = Bsm + buf*TILE_FLOATS;
        #pragma unroll
        for (int ks = 0; ks < 2; ks++) {
            u32 areg[4][4], breg[4][2];
            #pragma unroll
            for (int mi = 0; mi < 4; mi++) {
                const float* ap = Ab + (wm + mi*16 + g4)*SPAD + ks*8 + q4;
                areg[mi][0] = __float_as_uint(ap[0]);
                areg[mi][1] = __float_as_uint(ap[8*SPAD]);
                areg[mi][2] = __float_as_uint(ap[4]);
                areg[mi][3] = __float_as_uint(ap[8*SPAD + 4]);
            }
            #pragma unroll
            for (int ni = 0; ni < 4; ni++) {
                const float* bp = Bb + (wn + ni*8 + g4)*SPAD + ks*8 + q4;
                breg[ni][0] = __float_as_uint(bp[0]);
                breg[ni][1] = __float_as_uint(bp[4]);
            }
            #pragma unroll
            for (int mi = 0; mi < 4; mi++)
                #pragma unroll
                for (int ni = 0; ni < 4; ni++)
                    mma8(acc[mi][ni], areg[mi], breg[ni]);
        }
        buf = (buf + 1 == NSTAGE) ? 0 : buf + 1;
    }

    // ---- epilogue ----
    #pragma unroll
    for (int mi = 0; mi < 4; mi++) {
        #pragma unroll
        for (int h = 0; h < 2; h++) {
            int r = row0 + wm + mi*16 + g4 + h*8;
            if (r >= Meff) continue;
            int cr = sCe ? sCe[r] : r;
            float gmul = 1.f;
            if (EPI == 3) gmul = g_gate[(long)cr*EE + eid];
            if (EPI == 4) gmul = g_gsh[cr];
            if (EPI == 5) gmul = g_gate[((long)z*TT + cr)*EE + eid];
            float* crow = C + (long)cr*ldc;
            #pragma unroll
            for (int ni = 0; ni < 4; ni++) {
                int col = col0 + wn + ni*8 + 2*q4;
                float v0 = acc[mi][ni][h*2 + 0];
                float v1 = acc[mi][ni][h*2 + 1];
                if (EPI == 1 || EPI == 2 || EPI == 3 || EPI == 4) {
                    v0 += bias[col]; v1 += bias[col+1];
                }
                float2 o;
                if (EPI == 0)      { o.x = tf32f(v0); o.y = tf32f(v1); }
                else if (EPI == 1) { o.x = tf32f(gelu_f(v0)); o.y = tf32f(gelu_f(v1)); }
                else if (EPI == 2) { o.x = tf32f(v0); o.y = tf32f(v1); }
                else if (EPI == 3 || EPI == 5) {
                    float2 pv = *(float2*)(crow + col);
                    o.x = pv.x + v0*gmul; o.y = pv.y + v1*gmul;
                } else { o.x = v0*gmul; o.y = v1*gmul; }
                *(float2*)(crow + col) = o;
            }
        }
    }
}

// ---------------- host dispatch ----------------
static void set_smem_attrs() {
    static int done = 0;
    if (done) return;
    cudaFuncSetAttribute(mma_gemm<0>, cudaFuncAttributeMaxDynamicSharedMemorySize, SMEM_DYN);
    cudaFuncSetAttribute(mma_gemm<1>, cudaFuncAttributeMaxDynamicSharedMemorySize, SMEM_DYN);
    cudaFuncSetAttribute(mma_gemm<2>, cudaFuncAttributeMaxDynamicSharedMemorySize, SMEM_DYN);
    cudaFuncSetAttribute(mma_gemm<3>, cudaFuncAttributeMaxDynamicSharedMemorySize, SMEM_DYN);
    cudaFuncSetAttribute(mma_gemm<4>, cudaFuncAttributeMaxDynamicSharedMemorySize, SMEM_DYN);
    cudaFuncSetAttribute(mma_gemm<5>, cudaFuncAttributeMaxDynamicSharedMemorySize, SMEM_DYN);
    done = 1;
}

static void gemm(int epi, const float* A, const float* B, float* C, const float* bias,
                 int M, int N, int K, int lda, int ldb, int ldc,
                 int batch = 1, long sA = 0, long sB = 0, long sC = 0, int eid = 0,
                 const int* gA = 0, int gAstride = 0,
                 const int* sCi = 0, int sCstride = 0,
                 const int* cntp = 0, int cntZ = 0) {
    dim3 grid(N/128, (M+127)/128, batch);
    dim3 blk(256);
    switch (epi) {
        case 0: mma_gemm<0><<<grid,blk,SMEM_DYN>>>(A,B,C,bias,M,N,K,lda,ldb,ldc,sA,sB,sC,eid,gA,gAstride,sCi,sCstride,cntp,cntZ); break;
        case 1: mma_gemm<1><<<grid,blk,SMEM_DYN>>>(A,B,C,bias,M,N,K,lda,ldb,ldc,sA,sB,sC,eid,gA,gAstride,sCi,sCstride,cntp,cntZ); break;
        case 2: mma_gemm<2><<<grid,blk,SMEM_DYN>>>(A,B,C,bias,M,N,K,lda,ldb,ldc,sA,sB,sC,eid,gA,gAstride,sCi,sCstride,cntp,cntZ); break;
        case 3: mma_gemm<3><<<grid,blk,SMEM_DYN>>>(A,B,C,bias,M,N,K,lda,ldb,ldc,sA,sB,sC,eid,gA,gAstride,sCi,sCstride,cntp,cntZ); break;
        case 4: mma_gemm<4><<<grid,blk,SMEM_DYN>>>(A,B,C,bias,M,N,K,lda,ldb,ldc,sA,sB,sC,eid,gA,gAstride,sCi,sCstride,cntp,cntZ); break;
        case 5: mma_gemm<5><<<grid,blk,SMEM_DYN>>>(A,B,C,bias,M,N,K,lda,ldb,ldc,sA,sB,sC,eid,gA,gAstride,sCi,sCstride,cntp,cntZ); break;
    }
}

static void transpose(const float* in, float* out, int R, int C, int batch = 1) {
    dim3 grid((C+31)/32, (R+31)/32, batch);
    transpose_k<<<grid, dim3(32,8)>>>(in, out, R, C);
}

extern "C" void kernel_launch(void* const* d_in, const int* in_sizes, int n_in,
                              void* d_out, int out_size) {
    const float* x   = (const float*)d_in[0];
    const float* sw1 = (const float*)d_in[1];  const float* sb1 = (const float*)d_in[2];
    const float* sw2 = (const float*)d_in[3];  const float* sb2 = (const float*)d_in[4];
    const float* gw  = (const float*)d_in[5];  const float* gb  = (const float*)d_in[6];
    const float* rw  = (const float*)d_in[7];  const float* rb  = (const float*)d_in[8];
    const float* ck  = (const float*)d_in[9];
    const float* cw1 = (const float*)d_in[10]; const float* cb1 = (const float*)d_in[11];
    const float* cw2 = (const float*)d_in[12]; const float* cb2 = (const float*)d_in[13];
    const float* fw1 = (const float*)d_in[14]; const float* fb1 = (const float*)d_in[15];
    const float* fw2 = (const float*)d_in[16]; const float* fb2 = (const float*)d_in[17];
    const float* mw1 = (const float*)d_in[18]; const float* mb1 = (const float*)d_in[19];
    const float* mw2 = (const float*)d_in[20]; const float* mb2 = (const float*)d_in[21];
    float* out = (float*)d_out;

    set_smem_attrs();

    void* p;
    cudaGetSymbolAddress(&p, g_H);    float* H    = (float*)p;
    cudaGetSymbolAddress(&p, g_xc);   float* xc   = (float*)p;
    cudaGetSymbolAddress(&p, g_xr);   float* xr   = (float*)p;
    cudaGetSymbolAddress(&p, g_xT);   float* xT   = (float*)p;
    cudaGetSymbolAddress(&p, g_cat);  float* cat  = (float*)p;
    cudaGetSymbolAddress(&p, g_fo);   float* fo   = (float*)p;
    cudaGetSymbolAddress(&p, g_foT);  float* foT  = (float*)p;
    cudaGetSymbolAddress(&p, g_CiSi); float* CiSi = (float*)p;
    cudaGetSymbolAddress(&p, g_Acos); float* Acos = (float*)p;
    cudaGetSymbolAddress(&p, g_Asin); float* Asin = (float*)p;
    cudaGetSymbolAddress(&p, g_WT);   float* WT   = (float*)p;
    cudaGetSymbolAddress(&p, g_cnt);  int* cnt    = (int*)p;
    cudaGetSymbolAddress(&p, g_list); int* list   = (int*)p;
    cudaGetSymbolAddress(&p, g_cntb); int* cntb   = (int*)p;
    cudaGetSymbolAddress(&p, g_listb);int* listb  = (int*)p;

    const long M1 = 1048576L;
    float* sw1T = WT;
    float* sw2T = WT + 2*M1;
    float* mw1T = WT + 4*M1;
    float* mw2T = WT + 8*M1;
    float* cw1T = WT + 12*M1;
    float* cw2T = WT + 16*M1;
    float* fw1T = WT + 20*M1;
    float* fw2T = WT + 28*M1;

    const long NEL = (long)NTOK*DD;
    const int EW_BLOCKS = (int)((NEL + 255) / 256);

    init_fwd<<<(NF*TT + 255)/256, 256>>>();
    init_inv<<<(int)(((long)TT*KI + 255)/256), 256>>>();
    router_kernel<<<NTOK, 256>>>(x, rw, rb, gw, gb);
    zero_cnt<<<1, 32>>>();
    build_lists<<<(NTOK + 255)/256, 256>>>();
    aux_kernel<<<1, 256>>>(out, out_size);
    round_copy<<<EW_BLOCKS, 256>>>(x, xr, NEL);

    // shared expert (dense)
    transpose(sw1, sw1T, DD, FFD);
    gemm(1, xr, sw1T, H,   sb1, NTOK, FFD, DD,  DD,  DD,  FFD);
    transpose(sw2, sw2T, FFD, DD);
    gemm(4, H, sw2T, out, sb2, NTOK, DD,  FFD, FFD, FFD, DD);

    // plain MLP experts (eid 2,5) — sparse
    transpose(mw1, mw1T, DD, FFD, 2);
    transpose(mw2, mw2T, FFD, DD, 2);
    for (int j = 0; j < 2; j++) {
        int eid = j == 0 ? 2 : 5;
        gemm(1, xr, mw1T + (long)j*2*M1, H,   mb1 + j*FFD, NTOK, FFD, DD,  DD,  DD,  FFD,
             1,0,0,0, eid, list + (long)eid*NTOK, 0, 0, 0, cnt + eid, 0);
        gemm(3, H,  mw2T + (long)j*2*M1, out, mb2 + j*DD,  NTOK, DD,  FFD, FFD, FFD, DD,
             1,0,0,0, eid, 0, 0, list + (long)eid*NTOK, 0, cnt + eid, 0);
    }

    // conv experts (eid 0,3) — sparse
    transpose(cw1, cw1T, DD, FFD, 2);
    transpose(cw2, cw2T, FFD, DD, 2);
    for (int j = 0; j < 2; j++) {
        int eid = j == 0 ? 0 : 3;
        conv_kernel<<<EW_BLOCKS, 256>>>(x, ck + (long)j*DD*3, xc);
        gemm(1, xc, cw1T + (long)j*2*M1, H,   cb1 + j*FFD, NTOK, FFD, DD,  DD,  DD,  FFD,
             1,0,0,0, eid, list + (long)eid*NTOK, 0, 0, 0, cnt + eid, 0);
        gemm(3, H,  cw2T + (long)j*2*M1, out, cb2 + j*DD,  NTOK, DD,  FFD, FFD, FFD, DD,
             1,0,0,0, eid, 0, 0, list + (long)eid*NTOK, 0, cnt + eid, 0);
    }

    // fourier experts (eid 1,4): fwd DFT + per-frequency MLP dense; inverse DFT sparse rows
    transpose(fw1, fw1T, 2048, FFD, 2);
    transpose(fw2, fw2T, FFD, 2048, 2);
    transpose(x, xT, TT, DD, BSZ);
    gemm(0, Acos, xT, cat,        nullptr, NF, DD, TT, TT, TT, 2048, BSZ, 0, (long)DD*TT, (long)NF*2048);
    gemm(0, Asin, xT, cat + 1024, nullptr, NF, DD, TT, TT, TT, 2048, BSZ, 0, (long)DD*TT, (long)NF*2048);
    for (int j = 0; j < 2; j++) {
        int eid = j == 0 ? 1 : 4;
        gemm(1, cat, fw1T + (long)j*4*M1, H,  fb1 + j*FFD,  BSZ*NF, FFD,  2048, 2048, 2048, FFD);
        gemm(2, H,   fw2T + (long)j*4*M1, fo, fb2 + j*2048, BSZ*NF, 2048, FFD,  FFD,  FFD,  2048);
        transpose_fo<<<dim3(33, 32, BSZ), dim3(32,8)>>>(fo, foT, 0, 0);
        transpose_fo<<<dim3(33, 32, BSZ), dim3(32,8)>>>(fo, foT, 1024, NFP);
        gemm(5, CiSi, foT, out, nullptr, TT, DD, KI, KI, KI, DD,
             BSZ, 0, (long)DD*KI, (long)TT*DD, eid,
             listb + (long)j*BSZ*TT, TT, listb + (long)j*BSZ*TT, TT, cntb + j*BSZ, 1);
    }
}

// round 16
// speedup vs baseline: 3.3665x; 1.5193x over previous
#include <cuda_runtime.h>
#include <cuda_fp16.h>
#include <math.h>

#define BSZ 8
#define TT  2048
#define DD  1024
#define FFD 2048
#define EE  6
#define NTOK (BSZ*TT)
#define NF  1025
#define NFP 1056
#define KI  (2*NFP)

typedef unsigned int u32;
typedef unsigned long long u64;

// ---------------- scratch ----------------
__device__ float g_gate[NTOK*EE];
__device__ float g_gsh[NTOK];
__device__ float g_probs[NTOK*EE];
__device__ int   g_idx[NTOK*2];
__device__ int   g_cnt[EE];
__device__ int   g_list[EE*NTOK];
__device__ int   g_cntb[2*BSZ];
__device__ int   g_listb[2*BSZ*TT];
__device__ __half g_H[NTOK*(long)FFD];
__device__ __half g_xc[NTOK*(long)DD];
__device__ __half g_xr[NTOK*(long)DD];
__device__ __half g_xT[BSZ*(long)DD*TT];
__device__ __half g_cat[BSZ*(long)NF*2048];
__device__ __half g_fo[BSZ*(long)NF*2048];
__device__ __half g_foT[BSZ*(long)DD*KI];
__device__ __half g_CiSi[(long)TT*KI];
__device__ __half g_Acos[(long)NF*TT];
__device__ __half g_Asin[(long)NF*TT];
__device__ __half g_WTh[40u*1024u*1024u];

// ---------------- init: DFT bases (fp16 at rest) ----------------
__global__ void init_fwd() {
    int i = blockIdx.x*blockDim.x + threadIdx.x;
    if (i >= NF*TT) return;
    int k = i / TT, t = i % TT;
    int idx = (k*t) & (TT-1);
    float fr = (float)idx / (float)(TT/2);
    g_Acos[i] = __float2half_rn(cospif(fr));
    g_Asin[i] = __float2half_rn(-sinpif(fr));
}
__global__ void init_inv() {
    long i = (long)blockIdx.x*blockDim.x + threadIdx.x;
    if (i >= (long)TT*KI) return;
    int t = (int)(i / KI), kk = (int)(i % KI);
    int isimag = kk >= NFP;
    int k = isimag ? kk - NFP : kk;
    float v = 0.f;
    const float invT = 1.0f/(float)TT;
    if (k < NF) {
        int idx = (k*t) & (TT-1);
        float fr = (float)idx / (float)(TT/2);
        if (!isimag) {
            if (k == 0) v = invT;
            else if (k == TT/2) v = ((t & 1) ? -invT : invT);
            else v = 2.0f*cospif(fr)*invT;
        } else {
            if (k != 0 && k != TT/2) v = -2.0f*sinpif(fr)*invT;
        }
    }
    g_CiSi[i] = __float2half_rn(v);
}

// ---------------- router + gates (raw fp32 x) ----------------
__global__ void router_kernel(const float* __restrict__ x,
                              const float* __restrict__ rw, const float* __restrict__ rb,
                              const float* __restrict__ gw, const float* __restrict__ gb) {
    __shared__ float sx[DD];
    __shared__ float slog[8];
    int tok = blockIdx.x;
    const float* xr = x + (long)tok * DD;
    for (int i = threadIdx.x; i < DD; i += blockDim.x) sx[i] = xr[i];
    __syncthreads();
    int w = threadIdx.x >> 5, lane = threadIdx.x & 31;
    if (w < 7) {
        float acc = 0.f;
        if (w < 6) { for (int i = lane; i < DD; i += 32) acc += sx[i] * rw[i*EE + w]; }
        else       { for (int i = lane; i < DD; i += 32) acc += sx[i] * gw[i]; }
        #pragma unroll
        for (int o = 16; o > 0; o >>= 1) acc += __shfl_down_sync(0xffffffffu, acc, o);
        if (lane == 0) slog[w] = acc + (w < 6 ? rb[w] : gb[0]);
    }
    __syncthreads();
    if (threadIdx.x == 0) {
        float l[EE], mx = -1e30f;
        for (int e = 0; e < EE; e++) { l[e] = slog[e]; mx = fmaxf(mx, l[e]); }
        float den = 0.f;
        for (int e = 0; e < EE; e++) { l[e] = expf(l[e]-mx); den += l[e]; }
        float p[EE];
        for (int e = 0; e < EE; e++) { p[e] = l[e]/den; g_probs[tok*EE+e] = p[e]; g_gate[tok*EE+e] = 0.f; }
        int i1 = 0; for (int e = 1; e < EE; e++) if (p[e] > p[i1]) i1 = e;
        int i2 = (i1==0)?1:0;
        for (int e = 0; e < EE; e++) if (e != i1 && p[e] > p[i2]) i2 = e;
        g_gate[tok*EE+i1] = p[i1];
        g_gate[tok*EE+i2] = p[i2];
        g_idx[tok*2]   = i1;
        g_idx[tok*2+1] = i2;
        g_gsh[tok] = 1.0f/(1.0f+expf(-slog[6]));
    }
}

__global__ void zero_cnt() {
    if (threadIdx.x < EE) g_cnt[threadIdx.x] = 0;
    if (threadIdx.x < 2*BSZ) g_cntb[threadIdx.x] = 0;
}

__global__ void build_lists() {
    int n = blockIdx.x*blockDim.x + threadIdx.x;
    if (n >= NTOK) return;
    int b = n / TT, t = n % TT;
    #pragma unroll
    for (int s = 0; s < 2; s++) {
        int e = g_idx[n*2+s];
        int pos = atomicAdd(&g_cnt[e], 1);
        g_list[e*NTOK + pos] = n;
        if (e == 1 || e == 4) {
            int fj = (e == 1) ? 0 : 1;
            int pos2 = atomicAdd(&g_cntb[fj*BSZ + b], 1);
            g_listb[(fj*BSZ + b)*TT + pos2] = t;
        }
    }
}

__global__ void aux_kernel(float* __restrict__ out, int out_size) {
    __shared__ float sf[EE][256];
    __shared__ int   si[EE][256];
    float imp[EE]; int cnt[EE];
    for (int e = 0; e < EE; e++) { imp[e] = 0.f; cnt[e] = 0; }
    for (int n = threadIdx.x; n < NTOK; n += 256) {
        #pragma unroll
        for (int e = 0; e < EE; e++) imp[e] += g_probs[n*EE+e];
        cnt[g_idx[n*2]]++; cnt[g_idx[n*2+1]]++;
    }
    for (int e = 0; e < EE; e++) { sf[e][threadIdx.x] = imp[e]; si[e][threadIdx.x] = cnt[e]; }
    __syncthreads();
    for (int s = 128; s > 0; s >>= 1) {
        if (threadIdx.x < s)
            for (int e = 0; e < EE; e++) {
                sf[e][threadIdx.x] += sf[e][threadIdx.x+s];
                si[e][threadIdx.x] += si[e][threadIdx.x+s];
            }
        __syncthreads();
    }
    if (threadIdx.x == 0) {
        float aux = 0.f;
        for (int e = 0; e < EE; e++)
            aux += ((float)si[e][0] / (2.0f*(float)NTOK)) * (sf[e][0] / (float)NTOK);
        out[out_size-1] = (float)EE * aux;
    }
}

// ---------------- conv (fp32 in, fp16 out) ----------------
__global__ void conv_kernel(const float* __restrict__ x, const float* __restrict__ ck,
                            __half* __restrict__ xc) {
    long i = (long)blockIdx.x*blockDim.x + threadIdx.x;
    if (i >= (long)NTOK*DD) return;
    int d = (int)(i % DD);
    long td = i / DD;
    int t = (int)(td % TT);
    float k0 = ck[d*3], k1 = ck[d*3+1], k2 = ck[d*3+2];
    float c = x[i]*k1;
    if (t > 0)     c += x[i-DD]*k0;
    if (t < TT-1)  c += x[i+DD]*k2;
    xc[i] = __float2half_rn(x[i] + c);
}

__global__ void half_copy(const float* __restrict__ in, __half* __restrict__ out, long n) {
    long i = (long)blockIdx.x*blockDim.x + threadIdx.x;
    if (i < n) out[i] = __float2half_rn(in[i]);
}

// ---------------- transposes (fp16 out) ----------------
__global__ void transpose_k(const float* __restrict__ in, __half* __restrict__ out,
                            int R, int C) {
    __shared__ float t[32][33];
    in += (long)blockIdx.z * R * C;
    out += (long)blockIdx.z * R * C;
    int c0 = blockIdx.x*32, r0 = blockIdx.y*32;
    #pragma unroll
    for (int i = 0; i < 4; i++) {
        int r = r0 + threadIdx.y + i*8, c = c0 + threadIdx.x;
        t[threadIdx.y+i*8][threadIdx.x] = (r < R && c < C) ? in[(long)r*C + c] : 0.f;
    }
    __syncthreads();
    #pragma unroll
    for (int i = 0; i < 4; i++) {
        int c = c0 + threadIdx.y + i*8, r = r0 + threadIdx.x;
        if (c < C && r < R) out[(long)c*R + r] = __float2half_rn(t[threadIdx.x][threadIdx.y+i*8]);
    }
}

__global__ void transpose_fo(const __half* __restrict__ fo, __half* __restrict__ foT,
                             int coloff, int kbase) {
    __shared__ float t[32][33];
    int b = blockIdx.z;
    const __half* in = fo + (long)b*NF*2048;
    __half* ob = foT + (long)b*DD*KI;
    int k0 = blockIdx.x*32, d0 = blockIdx.y*32;
    #pragma unroll
    for (int i = 0; i < 4; i++) {
        int k = k0 + threadIdx.y + i*8;
        t[threadIdx.y+i*8][threadIdx.x] = (k < NF) ? __half2float(in[(long)k*2048 + coloff + d0 + threadIdx.x]) : 0.f;
    }
    __syncthreads();
    #pragma unroll
    for (int i = 0; i < 4; i++) {
        int d = d0 + threadIdx.y + i*8;
        ob[(long)d*KI + kbase + k0 + threadIdx.x] = __float2half_rn(t[threadIdx.x][threadIdx.y+i*8]);
    }
}

// ================= fp16 mma.sync GEMM (m16n8k16) with gather/scatter =================
// D[M,N] = A[M,K] @ Bt[N,K]^T; A,Bt fp16 K-major. K%32==0, N%128==0.
#define BK 32
#define PADH 40
#define TILE_HALFS (128*PADH)
#define NSTAGE 3
#define SMEM_DYN (NSTAGE*2*TILE_HALFS*2)

__device__ __forceinline__ float gelu_f(float v) {
    return 0.5f*v*(1.0f + erff(v*0.7071067811865475f));
}
__device__ __forceinline__ void cp16(u32 dst, const void* src, int sz) {
    asm volatile("cp.async.ca.shared.global [%0], [%1], 16, %2;" :: "r"(dst), "l"(src), "r"(sz));
}
__device__ __forceinline__ void mma16(float* c, const u32* a, const u32* b) {
    asm volatile("mma.sync.aligned.m16n8k16.row.col.f32.f16.f16.f32 "
        "{%0,%1,%2,%3}, {%4,%5,%6,%7}, {%8,%9}, {%0,%1,%2,%3};"
        : "+f"(c[0]), "+f"(c[1]), "+f"(c[2]), "+f"(c[3])
        : "r"(a[0]), "r"(a[1]), "r"(a[2]), "r"(a[3]), "r"(b[0]), "r"(b[1]));
}

// EPI: 0 h(v) store, 1 h(gelu(v+b)) store, 2 h(v+b) store,
//      3 out[cr]+=(v+b)*gate[cr,eid], 4 out=(v+b)*gsh[r], 5 out[cr]+=v*gate[z*TT+cr,eid]
template<int EPI>
__global__ void __launch_bounds__(256, 2)
mma_gemm(const __half* __restrict__ A, const __half* __restrict__ B,
         void* __restrict__ Cv, const float* __restrict__ bias,
         int M, int N, int K, int lda, int ldb, int ldc,
         long sA, long sB, long sC, int eid,
         const int* __restrict__ gA, int gAstride,
         const int* __restrict__ sCi, int sCstride,
         const int* __restrict__ cntp, int cntZ)
{
    const int z = blockIdx.z;
    const int Meff = cntp ? cntp[cntZ ? z : 0] : M;
    const int row0 = blockIdx.y * 128;
    if (row0 >= Meff) return;
    extern __shared__ __align__(16) char smraw[];
    __half* Asm = (__half*)smraw;
    __half* Bsm = Asm + NSTAGE*TILE_HALFS;
    A += (long)z * sA;
    B += (long)z * sB;
    const int col0 = blockIdx.x * 128;
    const int tid = threadIdx.x, lane = tid & 31, wid = tid >> 5;
    const int wm = (wid >> 2) * 64, wn = (wid & 3) * 32;
    const u32 sa = (u32)__cvta_generic_to_shared(Asm);
    const u32 sb = (u32)__cvta_generic_to_shared(Bsm);
    const int g4 = lane >> 2, q4 = lane & 3;
    const int* gAe = gA ? gA + (long)z*gAstride : (const int*)0;
    const int* sCe = sCi ? sCi + (long)z*sCstride : (const int*)0;

    float acc[4][4][4];
    #pragma unroll
    for (int mi = 0; mi < 4; mi++)
        #pragma unroll
        for (int ni = 0; ni < 4; ni++)
            #pragma unroll
            for (int q = 0; q < 4; q++) acc[mi][ni][q] = 0.f;

    const int ldrow = tid >> 1, ldq0 = (tid & 1)*2;  // row 0..127, quads {ldq0, ldq0+1}
    const int nk = K / BK;

    const int ra = row0 + ldrow;
    const bool okA = ra < Meff;
    const long aoff = okA ? (long)(gAe ? gAe[ra] : ra)*lda : 0;
    const long boff = (long)(col0 + ldrow)*ldb;

    auto loadStage = [&](int ic, int buf) {
        int k0 = ic * BK;
        const __half* Ap = A + aoff + k0;
        const __half* Bp = B + boff + k0;
        u32 abase = sa + (u32)((buf*TILE_HALFS + ldrow*PADH)*2);
        u32 bbase = sb + (u32)((buf*TILE_HALFS + ldrow*PADH)*2);
        #pragma unroll
        for (int qq = 0; qq < 2; qq++) {
            int quad = ldq0 + qq;
            cp16(abase + quad*16, Ap + quad*8, okA ? 16 : 0);
            cp16(bbase + quad*16, Bp + quad*8, 16);
        }
        asm volatile("cp.async.commit_group;" ::: "memory");
    };

    loadStage(0, 0);
    if (nk > 1) loadStage(1, 1);

    int buf = 0;
    for (int ic = 0; ic < nk; ic++) {
        asm volatile("cp.async.wait_group 1;" ::: "memory");
        __syncthreads();
        if (ic + 2 < nk) loadStage(ic + 2, (ic + 2) % NSTAGE);

        const u32* Ab = (const u32*)(Asm + buf*TILE_HALFS);
        const u32* Bb = (const u32*)(Bsm + buf*TILE_HALFS);
        #pragma unroll
        for (int ks = 0; ks < 2; ks++) {
            u32 areg[4][4], breg[4][2];
            #pragma unroll
            for (int mi = 0; mi < 4; mi++) {
                const u32* ap = Ab + (wm + mi*16 + g4)*(PADH/2) + ks*8 + q4;
                areg[mi][0] = ap[0];
                areg[mi][1] = ap[8*(PADH/2)];
                areg[mi][2] = ap[4];
                areg[mi][3] = ap[8*(PADH/2) + 4];
            }
            #pragma unroll
            for (int ni = 0; ni < 4; ni++) {
                const u32* bp = Bb + (wn + ni*8 + g4)*(PADH/2) + ks*8 + q4;
                breg[ni][0] = bp[0];
                breg[ni][1] = bp[4];
            }
            #pragma unroll
            for (int mi = 0; mi < 4; mi++)
                #pragma unroll
                for (int ni = 0; ni < 4; ni++)
                    mma16(acc[mi][ni], areg[mi], breg[ni]);
        }
        buf = (buf + 1 == NSTAGE) ? 0 : buf + 1;
    }

    // ---- epilogue (C frag: rows g4 / g4+8, cols 2*q4, 2*q4+1) ----
    #pragma unroll
    for (int mi = 0; mi < 4; mi++) {
        #pragma unroll
        for (int h = 0; h < 2; h++) {
            int r = row0 + wm + mi*16 + g4 + h*8;
            if (r >= Meff) continue;
            int cr = sCe ? sCe[r] : r;
            float gmul = 1.f;
            if (EPI == 3) gmul = g_gate[(long)cr*EE + eid];
            if (EPI == 4) gmul = g_gsh[cr];
            if (EPI == 5) gmul = g_gate[((long)z*TT + cr)*EE + eid];
            #pragma unroll
            for (int ni = 0; ni < 4; ni++) {
                int col = col0 + wn + ni*8 + 2*q4;
                float v0 = acc[mi][ni][h*2 + 0];
                float v1 = acc[mi][ni][h*2 + 1];
                if (EPI == 1 || EPI == 2 || EPI == 3 || EPI == 4) {
                    v0 += bias[col]; v1 += bias[col+1];
                }
                if (EPI <= 2) {
                    __half* crow = (__half*)Cv + (long)z*sC + (long)cr*ldc;
                    float o0 = v0, o1 = v1;
                    if (EPI == 1) { o0 = gelu_f(v0); o1 = gelu_f(v1); }
                    __half2 hv = __floats2half2_rn(o0, o1);
                    *(__half2*)(crow + col) = hv;
                } else {
                    float* crow = (float*)Cv + (long)z*sC + (long)cr*ldc;
                    float2 o;
                    if (EPI == 3 || EPI == 5) {
                        float2 pv = *(float2*)(crow + col);
                        o.x = pv.x + v0*gmul; o.y = pv.y + v1*gmul;
                    } else { o.x = v0*gmul; o.y = v1*gmul; }
                    *(float2*)(crow + col) = o;
                }
            }
        }
    }
}

// ---------------- host dispatch ----------------
static void set_smem_attrs() {
    static int done = 0;
    if (done) return;
    cudaFuncSetAttribute(mma_gemm<0>, cudaFuncAttributeMaxDynamicSharedMemorySize, SMEM_DYN);
    cudaFuncSetAttribute(mma_gemm<1>, cudaFuncAttributeMaxDynamicSharedMemorySize, SMEM_DYN);
    cudaFuncSetAttribute(mma_gemm<2>, cudaFuncAttributeMaxDynamicSharedMemorySize, SMEM_DYN);
    cudaFuncSetAttribute(mma_gemm<3>, cudaFuncAttributeMaxDynamicSharedMemorySize, SMEM_DYN);
    cudaFuncSetAttribute(mma_gemm<4>, cudaFuncAttributeMaxDynamicSharedMemorySize, SMEM_DYN);
    cudaFuncSetAttribute(mma_gemm<5>, cudaFuncAttributeMaxDynamicSharedMemorySize, SMEM_DYN);
    done = 1;
}

static void gemm(int epi, const __half* A, const __half* B, void* C, const float* bias,
                 int M, int N, int K, int lda, int ldb, int ldc,
                 int batch = 1, long sA = 0, long sB = 0, long sC = 0, int eid = 0,
                 const int* gA = 0, int gAstride = 0,
                 const int* sCi = 0, int sCstride = 0,
                 const int* cntp = 0, int cntZ = 0) {
    dim3 grid(N/128, (M+127)/128, batch);
    dim3 blk(256);
    switch (epi) {
        case 0: mma_gemm<0><<<grid,blk,SMEM_DYN>>>(A,B,C,bias,M,N,K,lda,ldb,ldc,sA,sB,sC,eid,gA,gAstride,sCi,sCstride,cntp,cntZ); break;
        case 1: mma_gemm<1><<<grid,blk,SMEM_DYN>>>(A,B,C,bias,M,N,K,lda,ldb,ldc,sA,sB,sC,eid,gA,gAstride,sCi,sCstride,cntp,cntZ); break;
        case 2: mma_gemm<2><<<grid,blk,SMEM_DYN>>>(A,B,C,bias,M,N,K,lda,ldb,ldc,sA,sB,sC,eid,gA,gAstride,sCi,sCstride,cntp,cntZ); break;
        case 3: mma_gemm<3><<<grid,blk,SMEM_DYN>>>(A,B,C,bias,M,N,K,lda,ldb,ldc,sA,sB,sC,eid,gA,gAstride,sCi,sCstride,cntp,cntZ); break;
        case 4: mma_gemm<4><<<grid,blk,SMEM_DYN>>>(A,B,C,bias,M,N,K,lda,ldb,ldc,sA,sB,sC,eid,gA,gAstride,sCi,sCstride,cntp,cntZ); break;
        case 5: mma_gemm<5><<<grid,blk,SMEM_DYN>>>(A,B,C,bias,M,N,K,lda,ldb,ldc,sA,sB,sC,eid,gA,gAstride,sCi,sCstride,cntp,cntZ); break;
    }
}

static void transpose(const float* in, __half* out, int R, int C, int batch = 1) {
    dim3 grid((C+31)/32, (R+31)/32, batch);
    transpose_k<<<grid, dim3(32,8)>>>(in, out, R, C);
}

extern "C" void kernel_launch(void* const* d_in, const int* in_sizes, int n_in,
                              void* d_out, int out_size) {
    const float* x   = (const float*)d_in[0];
    const float* sw1 = (const float*)d_in[1];  const float* sb1 = (const float*)d_in[2];
    const float* sw2 = (const float*)d_in[3];  const float* sb2 = (const float*)d_in[4];
    const float* gw  = (const float*)d_in[5];  const float* gb  = (const float*)d_in[6];
    const float* rw  = (const float*)d_in[7];  const float* rb  = (const float*)d_in[8];
    const float* ck  = (const float*)d_in[9];
    const float* cw1 = (const float*)d_in[10]; const float* cb1 = (const float*)d_in[11];
    const float* cw2 = (const float*)d_in[12]; const float* cb2 = (const float*)d_in[13];
    const float* fw1 = (const float*)d_in[14]; const float* fb1 = (const float*)d_in[15];
    const float* fw2 = (const float*)d_in[16]; const float* fb2 = (const float*)d_in[17];
    const float* mw1 = (const float*)d_in[18]; const float* mb1 = (const float*)d_in[19];
    const float* mw2 = (const float*)d_in[20]; const float* mb2 = (const float*)d_in[21];
    float* out = (float*)d_out;

    set_smem_attrs();

    void* p;
    cudaGetSymbolAddress(&p, g_H);    __half* H    = (__half*)p;
    cudaGetSymbolAddress(&p, g_xc);   __half* xc   = (__half*)p;
    cudaGetSymbolAddress(&p, g_xr);   __half* xr   = (__half*)p;
    cudaGetSymbolAddress(&p, g_xT);   __half* xT   = (__half*)p;
    cudaGetSymbolAddress(&p, g_cat);  __half* cat  = (__half*)p;
    cudaGetSymbolAddress(&p, g_fo);   __half* fo   = (__half*)p;
    cudaGetSymbolAddress(&p, g_foT);  __half* foT  = (__half*)p;
    cudaGetSymbolAddress(&p, g_CiSi); __half* CiSi = (__half*)p;
    cudaGetSymbolAddress(&p, g_Acos); __half* Acos = (__half*)p;
    cudaGetSymbolAddress(&p, g_Asin); __half* Asin = (__half*)p;
    cudaGetSymbolAddress(&p, g_WTh);  __half* WT   = (__half*)p;
    cudaGetSymbolAddress(&p, g_cnt);  int* cnt    = (int*)p;
    cudaGetSymbolAddress(&p, g_list); int* list   = (int*)p;
    cudaGetSymbolAddress(&p, g_cntb); int* cntb   = (int*)p;
    cudaGetSymbolAddress(&p, g_listb);int* listb  = (int*)p;

    const long M1 = 1048576L;
    __half* sw1T = WT;
    __half* sw2T = WT + 2*M1;
    __half* mw1T = WT + 4*M1;
    __half* mw2T = WT + 8*M1;
    __half* cw1T = WT + 12*M1;
    __half* cw2T = WT + 16*M1;
    __half* fw1T = WT + 20*M1;
    __half* fw2T = WT + 28*M1;

    const long NEL = (long)NTOK*DD;
    const int EW_BLOCKS = (int)((NEL + 255) / 256);

    init_fwd<<<(NF*TT + 255)/256, 256>>>();
    init_inv<<<(int)(((long)TT*KI + 255)/256), 256>>>();
    router_kernel<<<NTOK, 256>>>(x, rw, rb, gw, gb);
    zero_cnt<<<1, 32>>>();
    build_lists<<<(NTOK + 255)/256, 256>>>();
    aux_kernel<<<1, 256>>>(out, out_size);
    half_copy<<<EW_BLOCKS, 256>>>(x, xr, NEL);

    // shared expert (dense)
    transpose(sw1, sw1T, DD, FFD);
    gemm(1, xr, sw1T, H,   sb1, NTOK, FFD, DD,  DD,  DD,  FFD);
    transpose(sw2, sw2T, FFD, DD);
    gemm(4, H, sw2T, out, sb2, NTOK, DD,  FFD, FFD, FFD, DD);

    // plain MLP experts (eid 2,5) — sparse
    transpose(mw1, mw1T, DD, FFD, 2);
    transpose(mw2, mw2T, FFD, DD, 2);
    for (int j = 0; j < 2; j++) {
        int eid = j == 0 ? 2 : 5;
        gemm(1, xr, mw1T + (long)j*2*M1, H,   mb1 + j*FFD, NTOK, FFD, DD,  DD,  DD,  FFD,
             1,0,0,0, eid, list + (long)eid*NTOK, 0, 0, 0, cnt + eid, 0);
        gemm(3, H,  mw2T + (long)j*2*M1, out, mb2 + j*DD,  NTOK, DD,  FFD, FFD, FFD, DD,
             1,0,0,0, eid, 0, 0, list + (long)eid*NTOK, 0, cnt + eid, 0);
    }

    // conv experts (eid 0,3) — sparse
    transpose(cw1, cw1T, DD, FFD, 2);
    transpose(cw2, cw2T, FFD, DD, 2);
    for (int j = 0; j < 2; j++) {
        int eid = j == 0 ? 0 : 3;
        conv_kernel<<<EW_BLOCKS, 256>>>(x, ck + (long)j*DD*3, xc);
        gemm(1, xc, cw1T + (long)j*2*M1, H,   cb1 + j*FFD, NTOK, FFD, DD,  DD,  DD,  FFD,
             1,0,0,0, eid, list + (long)eid*NTOK, 0, 0, 0, cnt + eid, 0);
        gemm(3, H,  cw2T + (long)j*2*M1, out, cb2 + j*DD,  NTOK, DD,  FFD, FFD, FFD, DD,
             1,0,0,0, eid, 0, 0, list + (long)eid*NTOK, 0, cnt + eid, 0);
    }

    // fourier experts (eid 1,4)
    transpose(fw1, fw1T, 2048, FFD, 2);
    transpose(fw2, fw2T, FFD, 2048, 2);
    transpose(x, xT, TT, DD, BSZ);
    gemm(0, Acos, xT, cat,        nullptr, NF, DD, TT, TT, TT, 2048, BSZ, 0, (long)DD*TT, (long)NF*2048);
    gemm(0, Asin, xT, cat + 1024, nullptr, NF, DD, TT, TT, TT, 2048, BSZ, 0, (long)DD*TT, (long)NF*2048);
    for (int j = 0; j < 2; j++) {
        int eid = j == 0 ? 1 : 4;
        gemm(1, cat, fw1T + (long)j*4*M1, H,  fb1 + j*FFD,  BSZ*NF, FFD,  2048, 2048, 2048, FFD);
        gemm(2, H,   fw2T + (long)j*4*M1, fo, fb2 + j*2048, BSZ*NF, 2048, FFD,  FFD,  FFD,  2048);
        transpose_fo<<<dim3(33, 32, BSZ), dim3(32,8)>>>(fo, foT, 0, 0);
        transpose_fo<<<dim3(33, 32, BSZ), dim3(32,8)>>>(fo, foT, 1024, NFP);
        gemm(5, CiSi, foT, out, nullptr, TT, DD, KI, KI, KI, DD,
             BSZ, 0, (long)DD*KI, (long)TT*DD, eid,
             listb + (long)j*BSZ*TT, TT, listb + (long)j*BSZ*TT, TT, cntb + j*BSZ, 1);
    }
}